// round 4
// baseline (speedup 1.0000x reference)
#include <cuda_runtime.h>
#include <cuda_bf16.h>

// ---------------------------------------------------------------------------
// AdaptiveSpectralBlock: B=2, C=512, D=1024, K=64, FB=513
// Algebra:
//   spectrum = tokens @ A   (A[d, k(re)/64+k(im)] precomputed from DFT x P)
//   fr = Re(spectrum*gw + spectrum*mask*lw)
//   score[k](t=fr) = b2 + sum_j t^j * Acoef[j][k]   (exact-GELU Taylor moments)
//   weights = softmax_k(score); pooled = (weights*fr) @ E; out = LN(tokens+pooled)
// ---------------------------------------------------------------------------

#define Dm 1024
#define Kk 64
#define FB 513
#define NROWS 1024            // B*C
#define ROWS_PER_BLK 8
#define NCHUNK 128            // moment d-chunks (8 d each)
#define NJ 11                 // poly degree 0..10

// scratch (allocation-free rule: __device__ globals)
__device__ float g_cos[Dm];
__device__ float g_sin[Dm];
__device__ float g_A[Dm * 128];          // [d][0..63]=re coef, [64..127]=im coef
__device__ float g_WG[NJ * Dm];          // w2[d]*g_j(b1[d])
__device__ float g_Mpart[NCHUNK * Kk * NJ];
__device__ float g_Acoef[NJ * Kk];       // [j][k]

// gelu(y) = 0.5y + (1/sqrt(2pi)) (y^2 - y^4/6 + y^6/40 - y^8/336 + y^10/3456)
__constant__ float c_cp[NJ] = {
    0.0f, 0.5f,
    0.39894228040143270f, 0.0f,
   -0.06649038006690545f, 0.0f,
    0.00997355701003582f, 0.0f,
   -0.00118732821548045f, 0.0f,
    1.1543006956058354e-4f
};
__constant__ float c_binom[NJ][NJ] = {
    {1,0,0,0,0,0,0,0,0,0,0},
    {1,1,0,0,0,0,0,0,0,0,0},
    {1,2,1,0,0,0,0,0,0,0,0},
    {1,3,3,1,0,0,0,0,0,0,0},
    {1,4,6,4,1,0,0,0,0,0,0},
    {1,5,10,10,5,1,0,0,0,0,0},
    {1,6,15,20,15,6,1,0,0,0,0},
    {1,7,21,35,35,21,7,1,0,0,0},
    {1,8,28,56,70,56,28,8,1,0,0},
    {1,9,36,84,126,126,84,36,9,1,0},
    {1,10,45,120,210,252,210,120,45,10,1}
};

// ---------------------------------------------------------------- K0: trig
__global__ void k_trig() {
    int i = threadIdx.x;
    float s, c;
    sincospif((float)i * (2.0f / (float)Dm), &s, &c);
    g_cos[i] = c;
    g_sin[i] = s;
}

// ------------------------------------------------- K1: A[d][*] = trig @ P
// grid 256 blocks x 256 threads; each block: 4 d values x 64 k
__global__ void __launch_bounds__(256) k_buildA(const float* __restrict__ P) {
    __shared__ float sc[Dm];
    __shared__ float ss[Dm];
    int t = threadIdx.x;
    for (int i = t; i < Dm; i += 256) { sc[i] = g_cos[i]; ss[i] = g_sin[i]; }
    __syncthreads();
    int k = t & 63;
    int d = blockIdx.x * 4 + (t >> 6);
    float are = 0.f, aim = 0.f;
    #pragma unroll 4
    for (int f = 0; f < FB; ++f) {
        float pv = P[f * Kk + k];
        int idx = (f * d) & (Dm - 1);
        are = fmaf(sc[idx], pv, are);
        aim = fmaf(-ss[idx], pv, aim);
    }
    g_A[d * 128 + k]      = are;
    g_A[d * 128 + 64 + k] = aim;
}

// ---------------------------------- K2a: WG[j][d] = w2[d] * g_j(b1[d])
__global__ void k_wg(const float* __restrict__ b1, const float* __restrict__ w2) {
    int d = blockIdx.x * 256 + threadIdx.x;
    float b = b1[d], w = w2[d];
    float bp[NJ];
    bp[0] = 1.f;
    #pragma unroll
    for (int i = 1; i < NJ; ++i) bp[i] = bp[i - 1] * b;
    #pragma unroll
    for (int j = 0; j < NJ; ++j) {
        float g = 0.f;
        #pragma unroll
        for (int p = 1; p < NJ; ++p) {
            if (p >= j) g = fmaf(c_cp[p] * c_binom[p][j], bp[p - j], g);
        }
        g_WG[j * Dm + d] = w * g;
    }
}

// ----------------- K2b: m[k,d] = E @ w1 (per 8-d chunk) -> partial moments
// grid 128 blocks x 256 threads
__global__ void __launch_bounds__(256) k_moments(const float* __restrict__ E,
                                                 const float* __restrict__ W1) {
    __shared__ float sE[64 * 65];       // E[k][jj] tile, padded
    __shared__ float sW[64 * 8];        // w1[jj][dd] tile
    __shared__ float pm[4 * 64 * 9];    // per-rep partial m
    __shared__ float sWG[NJ * 8];
    __shared__ float msum[64 * 9];      // reduced m[k][dd] (dedicated, fully written)
    int t = threadIdx.x;
    int d0 = blockIdx.x * 8;
    int k = t & 63, rep = t >> 6;

    if (t < NJ * 8) {
        int j = t >> 3, dd = t & 7;
        sWG[t] = g_WG[j * Dm + d0 + dd];
    }
    float pa[8];
    #pragma unroll
    for (int i = 0; i < 8; ++i) pa[i] = 0.f;

    for (int jt = 0; jt < Dm; jt += 64) {
        #pragma unroll
        for (int i = 0; i < 16; ++i) {
            int lin = t + i * 256;
            int kk = lin >> 6, jj = lin & 63;
            sE[kk * 65 + jj] = E[kk * Dm + jt + jj];
        }
        #pragma unroll
        for (int i = 0; i < 2; ++i) {
            int lin = t + i * 256;          // lin = jj*8 + dd
            int jj = lin >> 3, dd = lin & 7;
            sW[lin] = W1[(jt + jj) * Dm + d0 + dd];
        }
        __syncthreads();
        int jb = rep * 16;
        #pragma unroll
        for (int q = 0; q < 16; ++q) {
            float e = sE[k * 65 + jb + q];
            float4 w0 = *(const float4*)&sW[(jb + q) * 8];
            float4 w1v = *(const float4*)&sW[(jb + q) * 8 + 4];
            pa[0] = fmaf(e, w0.x, pa[0]);
            pa[1] = fmaf(e, w0.y, pa[1]);
            pa[2] = fmaf(e, w0.z, pa[2]);
            pa[3] = fmaf(e, w0.w, pa[3]);
            pa[4] = fmaf(e, w1v.x, pa[4]);
            pa[5] = fmaf(e, w1v.y, pa[5]);
            pa[6] = fmaf(e, w1v.z, pa[6]);
            pa[7] = fmaf(e, w1v.w, pa[7]);
        }
        __syncthreads();
    }
    #pragma unroll
    for (int i = 0; i < 8; ++i) pm[rep * 576 + k * 9 + i] = pa[i];
    __syncthreads();
    // FIX (R3): reduce all 512 (k,dd) partials with 256 threads x 2 iterations.
    // (Previous code used `if (t < 512)` which covered only kk 0..31 and left
    // kk 32..63 reading stale/uninitialized shared memory -> garbage moments,
    // inflated high-power score coefficients, broken softmax -> rel_err 1.66e-2.)
    #pragma unroll
    for (int i = 0; i < 2; ++i) {
        int lin = t + i * 256;              // 0..511
        int kk = lin >> 3, dd = lin & 7;
        msum[kk * 9 + dd] = pm[0 * 576 + kk * 9 + dd] + pm[1 * 576 + kk * 9 + dd]
                          + pm[2 * 576 + kk * 9 + dd] + pm[3 * 576 + kk * 9 + dd];
    }
    __syncthreads();
    if (t < 64) {
        float acc[NJ];
        #pragma unroll
        for (int j = 0; j < NJ; ++j) acc[j] = 0.f;
        #pragma unroll
        for (int dd = 0; dd < 8; ++dd) {
            float m = msum[t * 9 + dd];
            float mp = 1.f;
            acc[0] += sWG[0 * 8 + dd];
            #pragma unroll
            for (int j = 1; j < NJ; ++j) {
                mp *= m;
                acc[j] = fmaf(mp, sWG[j * 8 + dd], acc[j]);
            }
        }
        #pragma unroll
        for (int j = 0; j < NJ; ++j)
            g_Mpart[blockIdx.x * (Kk * NJ) + t * NJ + j] = acc[j];
    }
}

// --------------------------------------- K2c: reduce moment partials
__global__ void k_mreduce() {
    int o = threadIdx.x;
    if (o >= Kk * NJ) return;
    float s = 0.f;
    for (int ch = 0; ch < NCHUNK; ++ch) s += g_Mpart[ch * (Kk * NJ) + o];
    int k = o / NJ, j = o % NJ;
    g_Acoef[j * Kk + k] = s;
}

// ------------------------------------------------------- K3: fused main
// grid 128 blocks x 256 threads, 8 rows per block
__global__ void __launch_bounds__(256) k_main(
    const float* __restrict__ tokens, const float* __restrict__ thr_p,
    const float* __restrict__ Gr, const float* __restrict__ Gi,
    const float* __restrict__ Lr, const float* __restrict__ Li,
    const float* __restrict__ E, const float* __restrict__ b2p,
    const float* __restrict__ gamma, const float* __restrict__ beta,
    float* __restrict__ out)
{
    __shared__ float xs[ROWS_PER_BLK * Dm];     // 32KB
    __shared__ float sp[ROWS_PER_BLK * 128];    // spectrum -> (score, fr)
    __shared__ float as_[ROWS_PER_BLK * 64];    // weights*fr
    __shared__ float ac[NJ * Kk];
    __shared__ float red1[8][8], red2[8][8];
    __shared__ float rmean[8], rrstd[8];

    int t = threadIdx.x;
    int row0 = blockIdx.x * ROWS_PER_BLK;
    int w = t >> 5, lane = t & 31;

    // stage tokens + coefficients
    {
        const float4* tok4 = (const float4*)(tokens + row0 * Dm);
        float4* xs4 = (float4*)xs;
        #pragma unroll
        for (int i = 0; i < 8; ++i) xs4[t + i * 256] = tok4[t + i * 256];
        for (int i = t; i < NJ * Kk; i += 256) ac[i] = g_Acoef[i];
    }
    __syncthreads();

    // ---- spectrum: row w, cols lane*4 .. lane*4+3 (re 0..63, im 64..127)
    {
        float a0 = 0.f, a1 = 0.f, a2 = 0.f, a3 = 0.f;
        const float* xrow = xs + w * Dm;
        const float4* Arow = (const float4*)g_A;
        for (int d = 0; d < Dm; d += 4) {
            float4 xv = *(const float4*)&xrow[d];
            float4 av;
            av = Arow[(d + 0) * 32 + lane];
            a0 = fmaf(xv.x, av.x, a0); a1 = fmaf(xv.x, av.y, a1);
            a2 = fmaf(xv.x, av.z, a2); a3 = fmaf(xv.x, av.w, a3);
            av = Arow[(d + 1) * 32 + lane];
            a0 = fmaf(xv.y, av.x, a0); a1 = fmaf(xv.y, av.y, a1);
            a2 = fmaf(xv.y, av.z, a2); a3 = fmaf(xv.y, av.w, a3);
            av = Arow[(d + 2) * 32 + lane];
            a0 = fmaf(xv.z, av.x, a0); a1 = fmaf(xv.z, av.y, a1);
            a2 = fmaf(xv.z, av.z, a2); a3 = fmaf(xv.z, av.w, a3);
            av = Arow[(d + 3) * 32 + lane];
            a0 = fmaf(xv.w, av.x, a0); a1 = fmaf(xv.w, av.y, a1);
            a2 = fmaf(xv.w, av.z, a2); a3 = fmaf(xv.w, av.w, a3);
        }
        sp[w * 128 + lane * 4 + 0] = a0;
        sp[w * 128 + lane * 4 + 1] = a1;
        sp[w * 128 + lane * 4 + 2] = a2;
        sp[w * 128 + lane * 4 + 3] = a3;
    }
    __syncthreads();

    float thr = thr_p[0];
    float b2v = b2p[0];

    // ---- filter + polynomial score (each (r,k) owned by one thread)
    #pragma unroll
    for (int pass = 0; pass < 2; ++pass) {
        int idx = t + pass * 256;
        int r = idx >> 6, k = idx & 63;
        int c = (row0 + r) & 511;
        float re = sp[r * 128 + k];
        float im = sp[r * 128 + 64 + k];
        float gr = Gr[c * Kk + k], gi = Gi[c * Kk + k];
        float lr = Lr[c * Kk + k], li = Li[c * Kk + k];
        float pw = fmaf(re, re, im * im);
        float fg = fmaf(re, gr, -im * gi);
        float fl = fmaf(re, lr, -im * li);
        float fr = (pw > thr) ? (fg + fl) : fg;
        float s = ac[10 * Kk + k];
        #pragma unroll
        for (int j = 9; j >= 0; --j) s = fmaf(s, fr, ac[j * Kk + k]);
        s += b2v;
        sp[r * 128 + k] = s;        // score
        sp[r * 128 + 64 + k] = fr;  // fr
    }
    __syncthreads();

    // ---- softmax per row (warp w -> row w), a = weight * fr
    {
        float s0 = sp[w * 128 + lane], s1 = sp[w * 128 + 32 + lane];
        float f0 = sp[w * 128 + 64 + lane], f1 = sp[w * 128 + 96 + lane];
        float mx = fmaxf(s0, s1);
        #pragma unroll
        for (int off = 16; off; off >>= 1)
            mx = fmaxf(mx, __shfl_xor_sync(0xffffffffu, mx, off));
        float e0 = __expf(s0 - mx), e1 = __expf(s1 - mx);
        float sm = e0 + e1;
        #pragma unroll
        for (int off = 16; off; off >>= 1)
            sm += __shfl_xor_sync(0xffffffffu, sm, off);
        float inv = 1.0f / sm;
        as_[w * 64 + lane]      = e0 * inv * f0;
        as_[w * 64 + 32 + lane] = e1 * inv * f1;
    }
    __syncthreads();

    // ---- pooled + LN stats
    {
        int d0 = t * 4;
        float4 acc[8];
        #pragma unroll
        for (int r = 0; r < 8; ++r) acc[r] = *(float4*)&xs[r * Dm + d0];
        for (int k = 0; k < 64; ++k) {
            float4 ev = *(const float4*)&E[k * Dm + d0];
            #pragma unroll
            for (int r = 0; r < 8; ++r) {
                float ar = as_[r * 64 + k];
                acc[r].x = fmaf(ar, ev.x, acc[r].x);
                acc[r].y = fmaf(ar, ev.y, acc[r].y);
                acc[r].z = fmaf(ar, ev.z, acc[r].z);
                acc[r].w = fmaf(ar, ev.w, acc[r].w);
            }
        }
        float s1l[8], s2l[8];
        #pragma unroll
        for (int r = 0; r < 8; ++r) {
            *(float4*)&xs[r * Dm + d0] = acc[r];
            s1l[r] = acc[r].x + acc[r].y + acc[r].z + acc[r].w;
            s2l[r] = acc[r].x * acc[r].x + acc[r].y * acc[r].y
                   + acc[r].z * acc[r].z + acc[r].w * acc[r].w;
        }
        #pragma unroll
        for (int r = 0; r < 8; ++r) {
            float a = s1l[r], b = s2l[r];
            #pragma unroll
            for (int off = 16; off; off >>= 1) {
                a += __shfl_xor_sync(0xffffffffu, a, off);
                b += __shfl_xor_sync(0xffffffffu, b, off);
            }
            if (lane == 0) { red1[r][w] = a; red2[r][w] = b; }
        }
    }
    __syncthreads();
    if (t < 8) {
        float s1 = 0.f, s2 = 0.f;
        #pragma unroll
        for (int i = 0; i < 8; ++i) { s1 += red1[t][i]; s2 += red2[t][i]; }
        float mean = s1 * (1.0f / 1024.0f);
        float var = fmaf(-mean, mean, s2 * (1.0f / 1024.0f));
        rmean[t] = mean;
        rrstd[t] = rsqrtf(var + 1e-5f);
    }
    __syncthreads();

    // ---- normalize + write
    {
        int d0 = t * 4;
        float4 g4 = *(const float4*)&gamma[d0];
        float4 b4 = *(const float4*)&beta[d0];
        #pragma unroll
        for (int r = 0; r < 8; ++r) {
            float4 v = *(float4*)&xs[r * Dm + d0];
            float mu = rmean[r], rs = rrstd[r];
            float4 o;
            o.x = fmaf((v.x - mu) * rs, g4.x, b4.x);
            o.y = fmaf((v.y - mu) * rs, g4.y, b4.y);
            o.z = fmaf((v.z - mu) * rs, g4.z, b4.z);
            o.w = fmaf((v.w - mu) * rs, g4.w, b4.w);
            *(float4*)&out[(row0 + r) * Dm + d0] = o;
        }
    }
}

// ---------------------------------------------------------------------------
extern "C" void kernel_launch(void* const* d_in, const int* in_sizes, int n_in,
                              void* d_out, int out_size) {
    const float* tokens = (const float*)d_in[0];
    const float* thresh = (const float*)d_in[1];
    const float* P      = (const float*)d_in[2];
    const float* Gr     = (const float*)d_in[3];
    const float* Gi     = (const float*)d_in[4];
    const float* Lr     = (const float*)d_in[5];
    const float* Li     = (const float*)d_in[6];
    const float* E      = (const float*)d_in[7];
    const float* W1     = (const float*)d_in[8];
    const float* b1     = (const float*)d_in[9];
    const float* w2     = (const float*)d_in[10];
    const float* b2     = (const float*)d_in[11];
    const float* gamma  = (const float*)d_in[12];
    const float* beta   = (const float*)d_in[13];
    float* out = (float*)d_out;

    k_trig<<<1, 1024>>>();
    k_buildA<<<256, 256>>>(P);
    k_wg<<<4, 256>>>(b1, w2);
    k_moments<<<NCHUNK, 256>>>(E, W1);
    k_mreduce<<<1, Kk * NJ>>>();
    k_main<<<NROWS / ROWS_PER_BLK, 256>>>(tokens, thresh, Gr, Gi, Lr, Li, E,
                                          b2, gamma, beta, out);
}

// round 5
// speedup vs baseline: 1.3332x; 1.3332x over previous
#include <cuda_runtime.h>
#include <cuda_bf16.h>

// ---------------------------------------------------------------------------
// AdaptiveSpectralBlock: B=2, C=512, D=1024, K=64, FB=513
//   spectrum = tokens @ A   (A precomputed from DFT x P)
//   fr = Re(spectrum*gw + spectrum*mask*lw)
//   score[k](t=fr) = b2 + sum_j t^j * Acoef[j][k]   (exact-GELU Taylor moments)
//   weights = softmax_k(score); pooled = (weights*fr) @ E; out = LN(tokens+pooled)
// ---------------------------------------------------------------------------

#define Dm 1024
#define Kk 64
#define FB 513
#define NROWS 1024            // B*C
#define ROWS_PER_BLK 8
#define NJ 11                 // poly degree 0..10
#define NSPLIT 8              // j-splits in E@W1 GEMM

// scratch (allocation-free rule: __device__ globals)
__device__ float g_A[Dm * 128];                 // [d][0..63]=re, [64..127]=im
__device__ float g_Mpart2[NSPLIT * Kk * Dm];    // partial m[k][d] per j-split
__device__ float g_Acoef[NJ * Kk];              // [j][k]

// gelu(y) = 0.5y + (1/sqrt(2pi)) (y^2 - y^4/6 + y^6/40 - y^8/336 + y^10/3456)
__constant__ float c_cp[NJ] = {
    0.0f, 0.5f,
    0.39894228040143270f, 0.0f,
   -0.06649038006690545f, 0.0f,
    0.00997355701003582f, 0.0f,
   -0.00118732821548045f, 0.0f,
    1.1543006956058354e-4f
};
__constant__ float c_binom[NJ][NJ] = {
    {1,0,0,0,0,0,0,0,0,0,0},
    {1,1,0,0,0,0,0,0,0,0,0},
    {1,2,1,0,0,0,0,0,0,0,0},
    {1,3,3,1,0,0,0,0,0,0,0},
    {1,4,6,4,1,0,0,0,0,0,0},
    {1,5,10,10,5,1,0,0,0,0,0},
    {1,6,15,20,15,6,1,0,0,0,0},
    {1,7,21,35,35,21,7,1,0,0,0},
    {1,8,28,56,70,56,28,8,1,0,0},
    {1,9,36,84,126,126,84,36,9,1,0},
    {1,10,45,120,210,252,210,120,45,10,1}
};

// ------------------------------------------------- K1: A[d][*] = trig @ P
// grid 128 blocks x 256 threads; block: 8 d values x 64 k, 2 d per thread.
__global__ void __launch_bounds__(256) k_buildA(const float* __restrict__ P) {
    __shared__ float2 stw[Dm];            // (cos, -sin) twiddles
    __shared__ float sP[128 * 64];        // P f-tile
    int t = threadIdx.x;

    #pragma unroll
    for (int i = 0; i < 4; ++i) {
        int idx = t + i * 256;
        float s, c;
        sincospif((float)idx * (2.0f / (float)Dm), &s, &c);
        stw[idx] = make_float2(c, -s);
    }

    int k = t & 63, dq = t >> 6;
    int d0 = blockIdx.x * 8;
    int da = d0 + dq, db = da + 4;
    float ara = 0.f, aia = 0.f, arb = 0.f, aib = 0.f;
    int ia = 0, ib = 0;                   // (f*d) & 1023 recurrences

    const float4* P4 = (const float4*)P;
    for (int f0 = 0; f0 < 512; f0 += 128) {
        __syncthreads();                  // protect sP reuse (also covers stw 1st time)
        #pragma unroll
        for (int i = 0; i < 8; ++i) {
            int lin4 = t + i * 256;       // 2048 float4 = 128 f x 16
            ((float4*)sP)[lin4] = P4[f0 * 16 + lin4];
        }
        __syncthreads();
        #pragma unroll 4
        for (int ff = 0; ff < 128; ++ff) {
            float2 wa = stw[ia];
            float2 wb = stw[ib];
            float pv = sP[ff * 64 + k];
            ara = fmaf(wa.x, pv, ara);
            aia = fmaf(wa.y, pv, aia);
            arb = fmaf(wb.x, pv, arb);
            aib = fmaf(wb.y, pv, aib);
            ia = (ia + da) & (Dm - 1);
            ib = (ib + db) & (Dm - 1);
        }
    }
    // Nyquist bin f=512: angle = pi*d -> cos = (-1)^d, sin = 0 (db same parity)
    float pn = P[512 * 64 + k];
    float sgn = (da & 1) ? -1.f : 1.f;
    ara = fmaf(sgn, pn, ara);
    arb = fmaf(sgn, pn, arb);

    g_A[da * 128 + k]      = ara;
    g_A[da * 128 + 64 + k] = aia;
    g_A[db * 128 + k]      = arb;
    g_A[db * 128 + 64 + k] = aib;
}

// --------------------- K2: m = E @ W1 split-K GEMM (partials per j-split)
// grid 128 = 16 d-tiles x 8 j-splits; 256 threads; thread = 4k x 4d tile.
__global__ void __launch_bounds__(256) k_gemm(const float* __restrict__ E,
                                              const float* __restrict__ W1) {
    __shared__ float sE[64 * 36];         // [k][jj], stride 36 (16B aligned)
    __shared__ float sW[32 * 64];         // [jj][d]
    int t = threadIdx.x;
    int bd = blockIdx.x & 15, bj = blockIdx.x >> 4;
    int d0 = bd * 64, j0 = bj * 128;
    int tk = (t >> 4) * 4;                // 0..60
    int tc = t & 15;                      // float4 column
    int td = tc * 4;

    float4 acc[4];
    #pragma unroll
    for (int r = 0; r < 4; ++r) acc[r] = make_float4(0.f, 0.f, 0.f, 0.f);

    const float4* E4 = (const float4*)E;
    const float4* W14 = (const float4*)W1;

    for (int js = 0; js < 128; js += 32) {
        __syncthreads();
        // E tile: rows 0..63, cols j0+js..+31 (512 float4, 2 per thread)
        #pragma unroll
        for (int i = 0; i < 2; ++i) {
            int lin4 = t + i * 256;
            int kr = lin4 >> 3, jc = lin4 & 7;
            float4 v = E4[kr * 256 + ((j0 + js) >> 2) + jc];
            *(float4*)&sE[kr * 36 + jc * 4] = v;
        }
        // W1 tile: rows j0+js..+31, cols d0..+63 (512 float4, 2 per thread)
        #pragma unroll
        for (int i = 0; i < 2; ++i) {
            int lin4 = t + i * 256;
            int jr = lin4 >> 4, dc = lin4 & 15;
            float4 v = W14[(j0 + js + jr) * 256 + (d0 >> 2) + dc];
            ((float4*)sW)[jr * 16 + dc] = v;
        }
        __syncthreads();
        #pragma unroll
        for (int jj = 0; jj < 32; ++jj) {
            float4 wv = ((float4*)sW)[jj * 16 + tc];
            float e0 = sE[(tk + 0) * 36 + jj];
            float e1 = sE[(tk + 1) * 36 + jj];
            float e2 = sE[(tk + 2) * 36 + jj];
            float e3 = sE[(tk + 3) * 36 + jj];
            acc[0].x = fmaf(e0, wv.x, acc[0].x); acc[0].y = fmaf(e0, wv.y, acc[0].y);
            acc[0].z = fmaf(e0, wv.z, acc[0].z); acc[0].w = fmaf(e0, wv.w, acc[0].w);
            acc[1].x = fmaf(e1, wv.x, acc[1].x); acc[1].y = fmaf(e1, wv.y, acc[1].y);
            acc[1].z = fmaf(e1, wv.z, acc[1].z); acc[1].w = fmaf(e1, wv.w, acc[1].w);
            acc[2].x = fmaf(e2, wv.x, acc[2].x); acc[2].y = fmaf(e2, wv.y, acc[2].y);
            acc[2].z = fmaf(e2, wv.z, acc[2].z); acc[2].w = fmaf(e2, wv.w, acc[2].w);
            acc[3].x = fmaf(e3, wv.x, acc[3].x); acc[3].y = fmaf(e3, wv.y, acc[3].y);
            acc[3].z = fmaf(e3, wv.z, acc[3].z); acc[3].w = fmaf(e3, wv.w, acc[3].w);
        }
    }
    #pragma unroll
    for (int r = 0; r < 4; ++r)
        *(float4*)&g_Mpart2[((bj << 6) + tk + r) * Dm + d0 + td] = acc[r];
}

// ----------- K3: reduce partials -> m; moments Acoef[j][k] (WG inline)
// grid 64 blocks (one per k) x 256 threads (4 d each)
__global__ void __launch_bounds__(256) k_powred(const float* __restrict__ b1,
                                                const float* __restrict__ w2) {
    __shared__ float red[8][NJ];
    int k = blockIdx.x, t = threadIdx.x;
    int d = t * 4;
    int w = t >> 5, lane = t & 31;

    float4 m4 = make_float4(0.f, 0.f, 0.f, 0.f);
    #pragma unroll
    for (int p = 0; p < NSPLIT; ++p) {
        float4 v = *(const float4*)&g_Mpart2[((p << 6) + k) * Dm + d];
        m4.x += v.x; m4.y += v.y; m4.z += v.z; m4.w += v.w;
    }
    float4 b4 = *(const float4*)&b1[d];
    float4 w4 = *(const float4*)&w2[d];

    float accj[NJ];
    #pragma unroll
    for (int j = 0; j < NJ; ++j) accj[j] = 0.f;

    float mlane[4] = {m4.x, m4.y, m4.z, m4.w};
    float blane[4] = {b4.x, b4.y, b4.z, b4.w};
    float wlane[4] = {w4.x, w4.y, w4.z, w4.w};
    #pragma unroll
    for (int q = 0; q < 4; ++q) {
        float bb = blane[q], ww = wlane[q], mm = mlane[q];
        float bp[NJ];
        bp[0] = 1.f;
        #pragma unroll
        for (int i = 1; i < NJ; ++i) bp[i] = bp[i - 1] * bb;
        float mp = 1.f;
        #pragma unroll
        for (int j = 0; j < NJ; ++j) {
            float gj = 0.f;
            #pragma unroll
            for (int p = 0; p < NJ; ++p) {
                if (p >= j) gj = fmaf(c_cp[p] * c_binom[p][j], bp[p - j], gj);
            }
            accj[j] = fmaf(ww * gj, mp, accj[j]);
            mp *= mm;
        }
    }
    // block reduce 11 values
    #pragma unroll
    for (int j = 0; j < NJ; ++j) {
        float a = accj[j];
        #pragma unroll
        for (int off = 16; off; off >>= 1)
            a += __shfl_xor_sync(0xffffffffu, a, off);
        if (lane == 0) red[w][j] = a;
    }
    __syncthreads();
    if (t < NJ) {
        float s = 0.f;
        #pragma unroll
        for (int i = 0; i < 8; ++i) s += red[i][t];
        g_Acoef[t * Kk + k] = s;
    }
}

// ------------------------------------------------------- K4: fused main
// grid 128 blocks x 256 threads, 8 rows per block  (unchanged from R3)
__global__ void __launch_bounds__(256) k_main(
    const float* __restrict__ tokens, const float* __restrict__ thr_p,
    const float* __restrict__ Gr, const float* __restrict__ Gi,
    const float* __restrict__ Lr, const float* __restrict__ Li,
    const float* __restrict__ E, const float* __restrict__ b2p,
    const float* __restrict__ gamma, const float* __restrict__ beta,
    float* __restrict__ out)
{
    __shared__ float xs[ROWS_PER_BLK * Dm];     // 32KB
    __shared__ float sp[ROWS_PER_BLK * 128];    // spectrum -> (score, fr)
    __shared__ float as_[ROWS_PER_BLK * 64];    // weights*fr
    __shared__ float ac[NJ * Kk];
    __shared__ float red1[8][8], red2[8][8];
    __shared__ float rmean[8], rrstd[8];

    int t = threadIdx.x;
    int row0 = blockIdx.x * ROWS_PER_BLK;
    int w = t >> 5, lane = t & 31;

    {
        const float4* tok4 = (const float4*)(tokens + row0 * Dm);
        float4* xs4 = (float4*)xs;
        #pragma unroll
        for (int i = 0; i < 8; ++i) xs4[t + i * 256] = tok4[t + i * 256];
        for (int i = t; i < NJ * Kk; i += 256) ac[i] = g_Acoef[i];
    }
    __syncthreads();

    // ---- spectrum: row w, cols lane*4 .. lane*4+3 (re 0..63, im 64..127)
    {
        float a0 = 0.f, a1 = 0.f, a2 = 0.f, a3 = 0.f;
        const float* xrow = xs + w * Dm;
        const float4* Arow = (const float4*)g_A;
        for (int d = 0; d < Dm; d += 4) {
            float4 xv = *(const float4*)&xrow[d];
            float4 av;
            av = Arow[(d + 0) * 32 + lane];
            a0 = fmaf(xv.x, av.x, a0); a1 = fmaf(xv.x, av.y, a1);
            a2 = fmaf(xv.x, av.z, a2); a3 = fmaf(xv.x, av.w, a3);
            av = Arow[(d + 1) * 32 + lane];
            a0 = fmaf(xv.y, av.x, a0); a1 = fmaf(xv.y, av.y, a1);
            a2 = fmaf(xv.y, av.z, a2); a3 = fmaf(xv.y, av.w, a3);
            av = Arow[(d + 2) * 32 + lane];
            a0 = fmaf(xv.z, av.x, a0); a1 = fmaf(xv.z, av.y, a1);
            a2 = fmaf(xv.z, av.z, a2); a3 = fmaf(xv.z, av.w, a3);
            av = Arow[(d + 3) * 32 + lane];
            a0 = fmaf(xv.w, av.x, a0); a1 = fmaf(xv.w, av.y, a1);
            a2 = fmaf(xv.w, av.z, a2); a3 = fmaf(xv.w, av.w, a3);
        }
        sp[w * 128 + lane * 4 + 0] = a0;
        sp[w * 128 + lane * 4 + 1] = a1;
        sp[w * 128 + lane * 4 + 2] = a2;
        sp[w * 128 + lane * 4 + 3] = a3;
    }
    __syncthreads();

    float thr = thr_p[0];
    float b2v = b2p[0];

    // ---- filter + polynomial score
    #pragma unroll
    for (int pass = 0; pass < 2; ++pass) {
        int idx = t + pass * 256;
        int r = idx >> 6, k = idx & 63;
        int c = (row0 + r) & 511;
        float re = sp[r * 128 + k];
        float im = sp[r * 128 + 64 + k];
        float gr = Gr[c * Kk + k], gi = Gi[c * Kk + k];
        float lr = Lr[c * Kk + k], li = Li[c * Kk + k];
        float pw = fmaf(re, re, im * im);
        float fg = fmaf(re, gr, -im * gi);
        float fl = fmaf(re, lr, -im * li);
        float fr = (pw > thr) ? (fg + fl) : fg;
        float s = ac[10 * Kk + k];
        #pragma unroll
        for (int j = 9; j >= 0; --j) s = fmaf(s, fr, ac[j * Kk + k]);
        s += b2v;
        sp[r * 128 + k] = s;        // score
        sp[r * 128 + 64 + k] = fr;  // fr
    }
    __syncthreads();

    // ---- softmax per row, a = weight * fr
    {
        float s0 = sp[w * 128 + lane], s1 = sp[w * 128 + 32 + lane];
        float f0 = sp[w * 128 + 64 + lane], f1 = sp[w * 128 + 96 + lane];
        float mx = fmaxf(s0, s1);
        #pragma unroll
        for (int off = 16; off; off >>= 1)
            mx = fmaxf(mx, __shfl_xor_sync(0xffffffffu, mx, off));
        float e0 = __expf(s0 - mx), e1 = __expf(s1 - mx);
        float sm = e0 + e1;
        #pragma unroll
        for (int off = 16; off; off >>= 1)
            sm += __shfl_xor_sync(0xffffffffu, sm, off);
        float inv = 1.0f / sm;
        as_[w * 64 + lane]      = e0 * inv * f0;
        as_[w * 64 + 32 + lane] = e1 * inv * f1;
    }
    __syncthreads();

    // ---- pooled + LN stats
    {
        int d0 = t * 4;
        float4 acc[8];
        #pragma unroll
        for (int r = 0; r < 8; ++r) acc[r] = *(float4*)&xs[r * Dm + d0];
        for (int k = 0; k < 64; ++k) {
            float4 ev = *(const float4*)&E[k * Dm + d0];
            #pragma unroll
            for (int r = 0; r < 8; ++r) {
                float ar = as_[r * 64 + k];
                acc[r].x = fmaf(ar, ev.x, acc[r].x);
                acc[r].y = fmaf(ar, ev.y, acc[r].y);
                acc[r].z = fmaf(ar, ev.z, acc[r].z);
                acc[r].w = fmaf(ar, ev.w, acc[r].w);
            }
        }
        float s1l[8], s2l[8];
        #pragma unroll
        for (int r = 0; r < 8; ++r) {
            *(float4*)&xs[r * Dm + d0] = acc[r];
            s1l[r] = acc[r].x + acc[r].y + acc[r].z + acc[r].w;
            s2l[r] = acc[r].x * acc[r].x + acc[r].y * acc[r].y
                   + acc[r].z * acc[r].z + acc[r].w * acc[r].w;
        }
        #pragma unroll
        for (int r = 0; r < 8; ++r) {
            float a = s1l[r], b = s2l[r];
            #pragma unroll
            for (int off = 16; off; off >>= 1) {
                a += __shfl_xor_sync(0xffffffffu, a, off);
                b += __shfl_xor_sync(0xffffffffu, b, off);
            }
            if (lane == 0) { red1[r][w] = a; red2[r][w] = b; }
        }
    }
    __syncthreads();
    if (t < 8) {
        float s1 = 0.f, s2 = 0.f;
        #pragma unroll
        for (int i = 0; i < 8; ++i) { s1 += red1[t][i]; s2 += red2[t][i]; }
        float mean = s1 * (1.0f / 1024.0f);
        float var = fmaf(-mean, mean, s2 * (1.0f / 1024.0f));
        rmean[t] = mean;
        rrstd[t] = rsqrtf(var + 1e-5f);
    }
    __syncthreads();

    // ---- normalize + write
    {
        int d0 = t * 4;
        float4 g4 = *(const float4*)&gamma[d0];
        float4 b4 = *(const float4*)&beta[d0];
        #pragma unroll
        for (int r = 0; r < 8; ++r) {
            float4 v = *(float4*)&xs[r * Dm + d0];
            float mu = rmean[r], rs = rrstd[r];
            float4 o;
            o.x = fmaf((v.x - mu) * rs, g4.x, b4.x);
            o.y = fmaf((v.y - mu) * rs, g4.y, b4.y);
            o.z = fmaf((v.z - mu) * rs, g4.z, b4.z);
            o.w = fmaf((v.w - mu) * rs, g4.w, b4.w);
            *(float4*)&out[(row0 + r) * Dm + d0] = o;
        }
    }
}

// ---------------------------------------------------------------------------
extern "C" void kernel_launch(void* const* d_in, const int* in_sizes, int n_in,
                              void* d_out, int out_size) {
    const float* tokens = (const float*)d_in[0];
    const float* thresh = (const float*)d_in[1];
    const float* P      = (const float*)d_in[2];
    const float* Gr     = (const float*)d_in[3];
    const float* Gi     = (const float*)d_in[4];
    const float* Lr     = (const float*)d_in[5];
    const float* Li     = (const float*)d_in[6];
    const float* E      = (const float*)d_in[7];
    const float* W1     = (const float*)d_in[8];
    const float* b1     = (const float*)d_in[9];
    const float* w2     = (const float*)d_in[10];
    const float* b2     = (const float*)d_in[11];
    const float* gamma  = (const float*)d_in[12];
    const float* beta   = (const float*)d_in[13];
    float* out = (float*)d_out;

    k_buildA<<<128, 256>>>(P);
    k_gemm<<<128, 256>>>(E, W1);
    k_powred<<<64, 256>>>(b1, w2);
    k_main<<<NROWS / ROWS_PER_BLK, 256>>>(tokens, thresh, Gr, Gi, Lr, Li, E,
                                          b2, gamma, beta, out);
}

// round 6
// speedup vs baseline: 1.6779x; 1.2586x over previous
#include <cuda_runtime.h>
#include <cuda_bf16.h>

// ---------------------------------------------------------------------------
// AdaptiveSpectralBlock: B=2, C=512, D=1024, K=64, FB=513
//   spectrum = tokens @ A   (A precomputed from DFT x P, stored transposed)
//   fr = Re(spectrum*gw + spectrum*mask*lw)
//   score[k](t=fr) = b2 + sum_j t^j * Acoef[j][k]   (exact-GELU Taylor moments)
//   weights = softmax_k(score); pooled = (weights*fr) @ E; out = LN(tokens+pooled)
// ---------------------------------------------------------------------------

#define Dm 1024
#define Kk 64
#define FB 513
#define NROWS 1024            // B*C
#define ROWS_PER_BLK 8
#define NJ 11                 // poly degree 0..10
#define NSPLIT 8              // j-splits in E@W1 GEMM

// scratch (allocation-free rule: __device__ globals)
__device__ float g_AT[128 * Dm];                // [col][d]; col 0..63 re, 64..127 im
__device__ float g_Mpart2[NSPLIT * Kk * Dm];    // partial m[k][d] per j-split
__device__ float g_Acoef[NJ * Kk];              // [j][k]

// gelu(y) = 0.5y + (1/sqrt(2pi)) (y^2 - y^4/6 + y^6/40 - y^8/336 + y^10/3456)
__constant__ float c_cp[NJ] = {
    0.0f, 0.5f,
    0.39894228040143270f, 0.0f,
   -0.06649038006690545f, 0.0f,
    0.00997355701003582f, 0.0f,
   -0.00118732821548045f, 0.0f,
    1.1543006956058354e-4f
};
__constant__ float c_binom[NJ][NJ] = {
    {1,0,0,0,0,0,0,0,0,0,0},
    {1,1,0,0,0,0,0,0,0,0,0},
    {1,2,1,0,0,0,0,0,0,0,0},
    {1,3,3,1,0,0,0,0,0,0,0},
    {1,4,6,4,1,0,0,0,0,0,0},
    {1,5,10,10,5,1,0,0,0,0,0},
    {1,6,15,20,15,6,1,0,0,0,0},
    {1,7,21,35,35,21,7,1,0,0,0},
    {1,8,28,56,70,56,28,8,1,0,0},
    {1,9,36,84,126,126,84,36,9,1,0},
    {1,10,45,120,210,252,210,120,45,10,1}
};

// ------------------------------------------------- K1: A^T[col][d] = (trig @ P)^T
// grid 128 blocks x 256 threads; block: 8 d values x 64 k, 2 d per thread.
__global__ void __launch_bounds__(256) k_buildA(const float* __restrict__ P) {
    __shared__ float2 stw[Dm];            // (cos, -sin) twiddles
    __shared__ float sP[128 * 64];        // P f-tile
    int t = threadIdx.x;

    #pragma unroll
    for (int i = 0; i < 4; ++i) {
        int idx = t + i * 256;
        float s, c;
        sincospif((float)idx * (2.0f / (float)Dm), &s, &c);
        stw[idx] = make_float2(c, -s);
    }

    int k = t & 63, dq = t >> 6;
    int d0 = blockIdx.x * 8;
    int da = d0 + dq, db = da + 4;
    float ara = 0.f, aia = 0.f, arb = 0.f, aib = 0.f;
    int ia = 0, ib = 0;                   // (f*d) & 1023 recurrences

    const float4* P4 = (const float4*)P;
    for (int f0 = 0; f0 < 512; f0 += 128) {
        __syncthreads();                  // protect sP reuse (also covers stw 1st time)
        #pragma unroll
        for (int i = 0; i < 8; ++i) {
            int lin4 = t + i * 256;       // 2048 float4 = 128 f x 16
            ((float4*)sP)[lin4] = P4[f0 * 16 + lin4];
        }
        __syncthreads();
        #pragma unroll 4
        for (int ff = 0; ff < 128; ++ff) {
            float2 wa = stw[ia];
            float2 wb = stw[ib];
            float pv = sP[ff * 64 + k];
            ara = fmaf(wa.x, pv, ara);
            aia = fmaf(wa.y, pv, aia);
            arb = fmaf(wb.x, pv, arb);
            aib = fmaf(wb.y, pv, aib);
            ia = (ia + da) & (Dm - 1);
            ib = (ib + db) & (Dm - 1);
        }
    }
    // Nyquist bin f=512: angle = pi*d -> cos = (-1)^d, sin = 0 (db same parity)
    float pn = P[512 * 64 + k];
    float sgn = (da & 1) ? -1.f : 1.f;
    ara = fmaf(sgn, pn, ara);
    arb = fmaf(sgn, pn, arb);

    // transposed stores: col-major rows of length Dm (one-time scattered write)
    g_AT[k * Dm + da]        = ara;
    g_AT[(64 + k) * Dm + da] = aia;
    g_AT[k * Dm + db]        = arb;
    g_AT[(64 + k) * Dm + db] = aib;
}

// --------------------- K2: m = E @ W1 split-K GEMM (partials per j-split)
// grid 128 = 16 d-tiles x 8 j-splits; 256 threads; thread = 4k x 4d tile.
__global__ void __launch_bounds__(256) k_gemm(const float* __restrict__ E,
                                              const float* __restrict__ W1) {
    __shared__ float sE[64 * 36];         // [k][jj], stride 36 (16B aligned)
    __shared__ float sW[32 * 64];         // [jj][d]
    int t = threadIdx.x;
    int bd = blockIdx.x & 15, bj = blockIdx.x >> 4;
    int d0 = bd * 64, j0 = bj * 128;
    int tk = (t >> 4) * 4;                // 0..60
    int tc = t & 15;                      // float4 column
    int td = tc * 4;

    float4 acc[4];
    #pragma unroll
    for (int r = 0; r < 4; ++r) acc[r] = make_float4(0.f, 0.f, 0.f, 0.f);

    const float4* E4 = (const float4*)E;
    const float4* W14 = (const float4*)W1;

    for (int js = 0; js < 128; js += 32) {
        __syncthreads();
        #pragma unroll
        for (int i = 0; i < 2; ++i) {
            int lin4 = t + i * 256;
            int kr = lin4 >> 3, jc = lin4 & 7;
            float4 v = E4[kr * 256 + ((j0 + js) >> 2) + jc];
            *(float4*)&sE[kr * 36 + jc * 4] = v;
        }
        #pragma unroll
        for (int i = 0; i < 2; ++i) {
            int lin4 = t + i * 256;
            int jr = lin4 >> 4, dc = lin4 & 15;
            float4 v = W14[(j0 + js + jr) * 256 + (d0 >> 2) + dc];
            ((float4*)sW)[jr * 16 + dc] = v;
        }
        __syncthreads();
        #pragma unroll
        for (int jj = 0; jj < 32; ++jj) {
            float4 wv = ((float4*)sW)[jj * 16 + tc];
            float e0 = sE[(tk + 0) * 36 + jj];
            float e1 = sE[(tk + 1) * 36 + jj];
            float e2 = sE[(tk + 2) * 36 + jj];
            float e3 = sE[(tk + 3) * 36 + jj];
            acc[0].x = fmaf(e0, wv.x, acc[0].x); acc[0].y = fmaf(e0, wv.y, acc[0].y);
            acc[0].z = fmaf(e0, wv.z, acc[0].z); acc[0].w = fmaf(e0, wv.w, acc[0].w);
            acc[1].x = fmaf(e1, wv.x, acc[1].x); acc[1].y = fmaf(e1, wv.y, acc[1].y);
            acc[1].z = fmaf(e1, wv.z, acc[1].z); acc[1].w = fmaf(e1, wv.w, acc[1].w);
            acc[2].x = fmaf(e2, wv.x, acc[2].x); acc[2].y = fmaf(e2, wv.y, acc[2].y);
            acc[2].z = fmaf(e2, wv.z, acc[2].z); acc[2].w = fmaf(e2, wv.w, acc[2].w);
            acc[3].x = fmaf(e3, wv.x, acc[3].x); acc[3].y = fmaf(e3, wv.y, acc[3].y);
            acc[3].z = fmaf(e3, wv.z, acc[3].z); acc[3].w = fmaf(e3, wv.w, acc[3].w);
        }
    }
    #pragma unroll
    for (int r = 0; r < 4; ++r)
        *(float4*)&g_Mpart2[((bj << 6) + tk + r) * Dm + d0 + td] = acc[r];
}

// ----------- K3: reduce partials -> m; moments Acoef[j][k] (WG inline)
// grid 64 blocks (one per k) x 256 threads (4 d each)
__global__ void __launch_bounds__(256) k_powred(const float* __restrict__ b1,
                                                const float* __restrict__ w2) {
    __shared__ float red[8][NJ];
    int k = blockIdx.x, t = threadIdx.x;
    int d = t * 4;
    int w = t >> 5, lane = t & 31;

    float4 m4 = make_float4(0.f, 0.f, 0.f, 0.f);
    #pragma unroll
    for (int p = 0; p < NSPLIT; ++p) {
        float4 v = *(const float4*)&g_Mpart2[((p << 6) + k) * Dm + d];
        m4.x += v.x; m4.y += v.y; m4.z += v.z; m4.w += v.w;
    }
    float4 b4 = *(const float4*)&b1[d];
    float4 w4 = *(const float4*)&w2[d];

    float accj[NJ];
    #pragma unroll
    for (int j = 0; j < NJ; ++j) accj[j] = 0.f;

    float mlane[4] = {m4.x, m4.y, m4.z, m4.w};
    float blane[4] = {b4.x, b4.y, b4.z, b4.w};
    float wlane[4] = {w4.x, w4.y, w4.z, w4.w};
    #pragma unroll
    for (int q = 0; q < 4; ++q) {
        float bb = blane[q], ww = wlane[q], mm = mlane[q];
        float bp[NJ];
        bp[0] = 1.f;
        #pragma unroll
        for (int i = 1; i < NJ; ++i) bp[i] = bp[i - 1] * bb;
        float mp = 1.f;
        #pragma unroll
        for (int j = 0; j < NJ; ++j) {
            float gj = 0.f;
            #pragma unroll
            for (int p = 0; p < NJ; ++p) {
                if (p >= j) gj = fmaf(c_cp[p] * c_binom[p][j], bp[p - j], gj);
            }
            accj[j] = fmaf(ww * gj, mp, accj[j]);
            mp *= mm;
        }
    }
    #pragma unroll
    for (int j = 0; j < NJ; ++j) {
        float a = accj[j];
        #pragma unroll
        for (int off = 16; off; off >>= 1)
            a += __shfl_xor_sync(0xffffffffu, a, off);
        if (lane == 0) red[w][j] = a;
    }
    __syncthreads();
    if (t < NJ) {
        float s = 0.f;
        #pragma unroll
        for (int i = 0; i < 8; ++i) s += red[i][t];
        g_Acoef[t * Kk + k] = s;
    }
}

// ------------------------------------------------------- K4: fused main
// grid 128 blocks x 256 threads, 8 rows per block
__global__ void __launch_bounds__(256) k_main(
    const float* __restrict__ tokens, const float* __restrict__ thr_p,
    const float* __restrict__ Gr, const float* __restrict__ Gi,
    const float* __restrict__ Lr, const float* __restrict__ Li,
    const float* __restrict__ E, const float* __restrict__ b2p,
    const float* __restrict__ gamma, const float* __restrict__ beta,
    float* __restrict__ out)
{
    __shared__ float xs[ROWS_PER_BLK * Dm];     // 32KB
    __shared__ float sp[ROWS_PER_BLK * 128];    // spectrum -> (score, fr)
    __shared__ float as_[ROWS_PER_BLK * 64];    // weights*fr
    __shared__ float ac[NJ * Kk];
    __shared__ float red1[8][8], red2[8][8];
    __shared__ float rmean[8], rrstd[8];

    int t = threadIdx.x;
    int row0 = blockIdx.x * ROWS_PER_BLK;
    int w = t >> 5, lane = t & 31;

    {
        const float4* tok4 = (const float4*)(tokens + row0 * Dm);
        float4* xs4 = (float4*)xs;
        #pragma unroll
        for (int i = 0; i < 8; ++i) xs4[t + i * 256] = tok4[t + i * 256];
        for (int i = t; i < NJ * Kk; i += 256) ac[i] = g_Acoef[i];
    }
    __syncthreads();

    // ---- spectrum (tokens @ A): warp w owns 16 cols; lane pair per col,
    //      d split into interleaved float4 halves; each lane does all 8 rows.
    //      A element read ONCE per block (8x reuse vs R5's once-per-row).
    {
        int c = (w << 4) + (lane >> 1);    // column 0..127
        int off = (lane & 1) << 2;         // 0 or 4 float offset
        float acc[8];
        #pragma unroll
        for (int r = 0; r < 8; ++r) acc[r] = 0.f;
        const float* Acol = g_AT + c * Dm;
        #pragma unroll 2
        for (int d = 0; d < Dm; d += 8) {
            float4 a4 = *(const float4*)&Acol[d + off];
            #pragma unroll
            for (int r = 0; r < 8; ++r) {
                float4 xv = *(const float4*)&xs[r * Dm + d + off];
                acc[r] = fmaf(xv.x, a4.x, acc[r]);
                acc[r] = fmaf(xv.y, a4.y, acc[r]);
                acc[r] = fmaf(xv.z, a4.z, acc[r]);
                acc[r] = fmaf(xv.w, a4.w, acc[r]);
            }
        }
        #pragma unroll
        for (int r = 0; r < 8; ++r)
            acc[r] += __shfl_xor_sync(0xffffffffu, acc[r], 1);
        if (!(lane & 1)) {
            #pragma unroll
            for (int r = 0; r < 8; ++r) sp[r * 128 + c] = acc[r];
        }
    }
    __syncthreads();

    float thr = thr_p[0];
    float b2v = b2p[0];

    // ---- filter + polynomial score
    #pragma unroll
    for (int pass = 0; pass < 2; ++pass) {
        int idx = t + pass * 256;
        int r = idx >> 6, k = idx & 63;
        int c = (row0 + r) & 511;
        float re = sp[r * 128 + k];
        float im = sp[r * 128 + 64 + k];
        float gr = Gr[c * Kk + k], gi = Gi[c * Kk + k];
        float lr = Lr[c * Kk + k], li = Li[c * Kk + k];
        float pw = fmaf(re, re, im * im);
        float fg = fmaf(re, gr, -im * gi);
        float fl = fmaf(re, lr, -im * li);
        float fr = (pw > thr) ? (fg + fl) : fg;
        float s = ac[10 * Kk + k];
        #pragma unroll
        for (int j = 9; j >= 0; --j) s = fmaf(s, fr, ac[j * Kk + k]);
        s += b2v;
        sp[r * 128 + k] = s;        // score
        sp[r * 128 + 64 + k] = fr;  // fr
    }
    __syncthreads();

    // ---- softmax per row, a = weight * fr
    {
        float s0 = sp[w * 128 + lane], s1 = sp[w * 128 + 32 + lane];
        float f0 = sp[w * 128 + 64 + lane], f1 = sp[w * 128 + 96 + lane];
        float mx = fmaxf(s0, s1);
        #pragma unroll
        for (int off = 16; off; off >>= 1)
            mx = fmaxf(mx, __shfl_xor_sync(0xffffffffu, mx, off));
        float e0 = __expf(s0 - mx), e1 = __expf(s1 - mx);
        float sm = e0 + e1;
        #pragma unroll
        for (int off = 16; off; off >>= 1)
            sm += __shfl_xor_sync(0xffffffffu, sm, off);
        float inv = 1.0f / sm;
        as_[w * 64 + lane]      = e0 * inv * f0;
        as_[w * 64 + 32 + lane] = e1 * inv * f1;
    }
    __syncthreads();

    // ---- pooled + LN stats
    {
        int d0 = t * 4;
        float4 acc[8];
        #pragma unroll
        for (int r = 0; r < 8; ++r) acc[r] = *(float4*)&xs[r * Dm + d0];
        for (int k = 0; k < 64; ++k) {
            float4 ev = *(const float4*)&E[k * Dm + d0];
            #pragma unroll
            for (int r = 0; r < 8; ++r) {
                float ar = as_[r * 64 + k];
                acc[r].x = fmaf(ar, ev.x, acc[r].x);
                acc[r].y = fmaf(ar, ev.y, acc[r].y);
                acc[r].z = fmaf(ar, ev.z, acc[r].z);
                acc[r].w = fmaf(ar, ev.w, acc[r].w);
            }
        }
        float s1l[8], s2l[8];
        #pragma unroll
        for (int r = 0; r < 8; ++r) {
            *(float4*)&xs[r * Dm + d0] = acc[r];
            s1l[r] = acc[r].x + acc[r].y + acc[r].z + acc[r].w;
            s2l[r] = acc[r].x * acc[r].x + acc[r].y * acc[r].y
                   + acc[r].z * acc[r].z + acc[r].w * acc[r].w;
        }
        #pragma unroll
        for (int r = 0; r < 8; ++r) {
            float a = s1l[r], b = s2l[r];
            #pragma unroll
            for (int off = 16; off; off >>= 1) {
                a += __shfl_xor_sync(0xffffffffu, a, off);
                b += __shfl_xor_sync(0xffffffffu, b, off);
            }
            if (lane == 0) { red1[r][w] = a; red2[r][w] = b; }
        }
    }
    __syncthreads();
    if (t < 8) {
        float s1 = 0.f, s2 = 0.f;
        #pragma unroll
        for (int i = 0; i < 8; ++i) { s1 += red1[t][i]; s2 += red2[t][i]; }
        float mean = s1 * (1.0f / 1024.0f);
        float var = fmaf(-mean, mean, s2 * (1.0f / 1024.0f));
        rmean[t] = mean;
        rrstd[t] = rsqrtf(var + 1e-5f);
    }
    __syncthreads();

    // ---- normalize + write
    {
        int d0 = t * 4;
        float4 g4 = *(const float4*)&gamma[d0];
        float4 b4 = *(const float4*)&beta[d0];
        #pragma unroll
        for (int r = 0; r < 8; ++r) {
            float4 v = *(float4*)&xs[r * Dm + d0];
            float mu = rmean[r], rs = rrstd[r];
            float4 o;
            o.x = fmaf((v.x - mu) * rs, g4.x, b4.x);
            o.y = fmaf((v.y - mu) * rs, g4.y, b4.y);
            o.z = fmaf((v.z - mu) * rs, g4.z, b4.z);
            o.w = fmaf((v.w - mu) * rs, g4.w, b4.w);
            *(float4*)&out[(row0 + r) * Dm + d0] = o;
        }
    }
}

// ---------------------------------------------------------------------------
extern "C" void kernel_launch(void* const* d_in, const int* in_sizes, int n_in,
                              void* d_out, int out_size) {
    const float* tokens = (const float*)d_in[0];
    const float* thresh = (const float*)d_in[1];
    const float* P      = (const float*)d_in[2];
    const float* Gr     = (const float*)d_in[3];
    const float* Gi     = (const float*)d_in[4];
    const float* Lr     = (const float*)d_in[5];
    const float* Li     = (const float*)d_in[6];
    const float* E      = (const float*)d_in[7];
    const float* W1     = (const float*)d_in[8];
    const float* b1     = (const float*)d_in[9];
    const float* w2     = (const float*)d_in[10];
    const float* b2     = (const float*)d_in[11];
    const float* gamma  = (const float*)d_in[12];
    const float* beta   = (const float*)d_in[13];
    float* out = (float*)d_out;

    k_buildA<<<128, 256>>>(P);
    k_gemm<<<128, 256>>>(E, W1);
    k_powred<<<64, 256>>>(b1, w2);
    k_main<<<NROWS / ROWS_PER_BLK, 256>>>(tokens, thresh, Gr, Gi, Lr, Li, E,
                                          b2, gamma, beta, out);
}

// round 7
// speedup vs baseline: 2.0575x; 1.2262x over previous
#include <cuda_runtime.h>
#include <cuda_bf16.h>

// ---------------------------------------------------------------------------
// AdaptiveSpectralBlock: B=2, C=512, D=1024, K=64, FB=513
//   spectrum = tokens @ A   (A precomputed from DFT x P, stored transposed)
//   fr = Re(spectrum*gw + spectrum*mask*lw)
//   score[k](t=fr) = b2 + sum_j t^j * Acoef[j][k]   (exact-GELU Taylor moments)
//   weights = softmax_k(score); pooled = (weights*fr) @ E; out = LN(tokens+pooled)
// ---------------------------------------------------------------------------

#define Dm 1024
#define Kk 64
#define FB 513
#define NROWS 1024            // B*C
#define ROWS_PER_BLK 8
#define NJ 11                 // poly degree 0..10
#define NSPLIT 8              // j-splits in E@W1 GEMM

// scratch (allocation-free rule: __device__ globals)
__device__ float g_AT[128 * Dm];                // [col][d]; col 0..63 re, 64..127 im
__device__ float g_Mpart2[NSPLIT * Kk * Dm];    // partial m[k][d] per j-split
__device__ float g_Acoef[NJ * Kk];              // [j][k]

// gelu(y) = 0.5y + (1/sqrt(2pi)) (y^2 - y^4/6 + y^6/40 - y^8/336 + y^10/3456)
__constant__ float c_cp[NJ] = {
    0.0f, 0.5f,
    0.39894228040143270f, 0.0f,
   -0.06649038006690545f, 0.0f,
    0.00997355701003582f, 0.0f,
   -0.00118732821548045f, 0.0f,
    1.1543006956058354e-4f
};
__constant__ float c_binom[NJ][NJ] = {
    {1,0,0,0,0,0,0,0,0,0,0},
    {1,1,0,0,0,0,0,0,0,0,0},
    {1,2,1,0,0,0,0,0,0,0,0},
    {1,3,3,1,0,0,0,0,0,0,0},
    {1,4,6,4,1,0,0,0,0,0,0},
    {1,5,10,10,5,1,0,0,0,0,0},
    {1,6,15,20,15,6,1,0,0,0,0},
    {1,7,21,35,35,21,7,1,0,0,0},
    {1,8,28,56,70,56,28,8,1,0,0},
    {1,9,36,84,126,126,84,36,9,1,0},
    {1,10,45,120,210,252,210,120,45,10,1}
};

// ------------------------------------------------- K1: A^T[col][d] = (trig @ P)^T
__global__ void __launch_bounds__(256) k_buildA(const float* __restrict__ P) {
    __shared__ float2 stw[Dm];            // (cos, -sin) twiddles
    __shared__ float sP[128 * 64];        // P f-tile
    int t = threadIdx.x;

    #pragma unroll
    for (int i = 0; i < 4; ++i) {
        int idx = t + i * 256;
        float s, c;
        sincospif((float)idx * (2.0f / (float)Dm), &s, &c);
        stw[idx] = make_float2(c, -s);
    }

    int k = t & 63, dq = t >> 6;
    int d0 = blockIdx.x * 8;
    int da = d0 + dq, db = da + 4;
    float ara = 0.f, aia = 0.f, arb = 0.f, aib = 0.f;
    int ia = 0, ib = 0;                   // (f*d) & 1023 recurrences

    const float4* P4 = (const float4*)P;
    for (int f0 = 0; f0 < 512; f0 += 128) {
        __syncthreads();
        #pragma unroll
        for (int i = 0; i < 8; ++i) {
            int lin4 = t + i * 256;
            ((float4*)sP)[lin4] = P4[f0 * 16 + lin4];
        }
        __syncthreads();
        #pragma unroll 4
        for (int ff = 0; ff < 128; ++ff) {
            float2 wa = stw[ia];
            float2 wb = stw[ib];
            float pv = sP[ff * 64 + k];
            ara = fmaf(wa.x, pv, ara);
            aia = fmaf(wa.y, pv, aia);
            arb = fmaf(wb.x, pv, arb);
            aib = fmaf(wb.y, pv, aib);
            ia = (ia + da) & (Dm - 1);
            ib = (ib + db) & (Dm - 1);
        }
    }
    float pn = P[512 * 64 + k];
    float sgn = (da & 1) ? -1.f : 1.f;
    ara = fmaf(sgn, pn, ara);
    arb = fmaf(sgn, pn, arb);

    g_AT[k * Dm + da]        = ara;
    g_AT[(64 + k) * Dm + da] = aia;
    g_AT[k * Dm + db]        = arb;
    g_AT[(64 + k) * Dm + db] = aib;
}

// --------------------- K2: m = E @ W1 split-K GEMM (partials per j-split)
__global__ void __launch_bounds__(256) k_gemm(const float* __restrict__ E,
                                              const float* __restrict__ W1) {
    __shared__ float sE[64 * 36];
    __shared__ float sW[32 * 64];
    int t = threadIdx.x;
    int bd = blockIdx.x & 15, bj = blockIdx.x >> 4;
    int d0 = bd * 64, j0 = bj * 128;
    int tk = (t >> 4) * 4;
    int tc = t & 15;
    int td = tc * 4;

    float4 acc[4];
    #pragma unroll
    for (int r = 0; r < 4; ++r) acc[r] = make_float4(0.f, 0.f, 0.f, 0.f);

    const float4* E4 = (const float4*)E;
    const float4* W14 = (const float4*)W1;

    for (int js = 0; js < 128; js += 32) {
        __syncthreads();
        #pragma unroll
        for (int i = 0; i < 2; ++i) {
            int lin4 = t + i * 256;
            int kr = lin4 >> 3, jc = lin4 & 7;
            float4 v = E4[kr * 256 + ((j0 + js) >> 2) + jc];
            *(float4*)&sE[kr * 36 + jc * 4] = v;
        }
        #pragma unroll
        for (int i = 0; i < 2; ++i) {
            int lin4 = t + i * 256;
            int jr = lin4 >> 4, dc = lin4 & 15;
            float4 v = W14[(j0 + js + jr) * 256 + (d0 >> 2) + dc];
            ((float4*)sW)[jr * 16 + dc] = v;
        }
        __syncthreads();
        #pragma unroll
        for (int jj = 0; jj < 32; ++jj) {
            float4 wv = ((float4*)sW)[jj * 16 + tc];
            float e0 = sE[(tk + 0) * 36 + jj];
            float e1 = sE[(tk + 1) * 36 + jj];
            float e2 = sE[(tk + 2) * 36 + jj];
            float e3 = sE[(tk + 3) * 36 + jj];
            acc[0].x = fmaf(e0, wv.x, acc[0].x); acc[0].y = fmaf(e0, wv.y, acc[0].y);
            acc[0].z = fmaf(e0, wv.z, acc[0].z); acc[0].w = fmaf(e0, wv.w, acc[0].w);
            acc[1].x = fmaf(e1, wv.x, acc[1].x); acc[1].y = fmaf(e1, wv.y, acc[1].y);
            acc[1].z = fmaf(e1, wv.z, acc[1].z); acc[1].w = fmaf(e1, wv.w, acc[1].w);
            acc[2].x = fmaf(e2, wv.x, acc[2].x); acc[2].y = fmaf(e2, wv.y, acc[2].y);
            acc[2].z = fmaf(e2, wv.z, acc[2].z); acc[2].w = fmaf(e2, wv.w, acc[2].w);
            acc[3].x = fmaf(e3, wv.x, acc[3].x); acc[3].y = fmaf(e3, wv.y, acc[3].y);
            acc[3].z = fmaf(e3, wv.z, acc[3].z); acc[3].w = fmaf(e3, wv.w, acc[3].w);
        }
    }
    #pragma unroll
    for (int r = 0; r < 4; ++r)
        *(float4*)&g_Mpart2[((bj << 6) + tk + r) * Dm + d0 + td] = acc[r];
}

// ----------- K3: reduce partials -> m; moments Acoef[j][k] (WG inline)
__global__ void __launch_bounds__(256) k_powred(const float* __restrict__ b1,
                                                const float* __restrict__ w2) {
    __shared__ float red[8][NJ];
    int k = blockIdx.x, t = threadIdx.x;
    int d = t * 4;
    int w = t >> 5, lane = t & 31;

    float4 m4 = make_float4(0.f, 0.f, 0.f, 0.f);
    #pragma unroll
    for (int p = 0; p < NSPLIT; ++p) {
        float4 v = *(const float4*)&g_Mpart2[((p << 6) + k) * Dm + d];
        m4.x += v.x; m4.y += v.y; m4.z += v.z; m4.w += v.w;
    }
    float4 b4 = *(const float4*)&b1[d];
    float4 w4 = *(const float4*)&w2[d];

    float accj[NJ];
    #pragma unroll
    for (int j = 0; j < NJ; ++j) accj[j] = 0.f;

    float mlane[4] = {m4.x, m4.y, m4.z, m4.w};
    float blane[4] = {b4.x, b4.y, b4.z, b4.w};
    float wlane[4] = {w4.x, w4.y, w4.z, w4.w};
    #pragma unroll
    for (int q = 0; q < 4; ++q) {
        float bb = blane[q], ww = wlane[q], mm = mlane[q];
        float bp[NJ];
        bp[0] = 1.f;
        #pragma unroll
        for (int i = 1; i < NJ; ++i) bp[i] = bp[i - 1] * bb;
        float mp = 1.f;
        #pragma unroll
        for (int j = 0; j < NJ; ++j) {
            float gj = 0.f;
            #pragma unroll
            for (int p = 0; p < NJ; ++p) {
                if (p >= j) gj = fmaf(c_cp[p] * c_binom[p][j], bp[p - j], gj);
            }
            accj[j] = fmaf(ww * gj, mp, accj[j]);
            mp *= mm;
        }
    }
    #pragma unroll
    for (int j = 0; j < NJ; ++j) {
        float a = accj[j];
        #pragma unroll
        for (int off = 16; off; off >>= 1)
            a += __shfl_xor_sync(0xffffffffu, a, off);
        if (lane == 0) red[w][j] = a;
    }
    __syncthreads();
    if (t < NJ) {
        float s = 0.f;
        #pragma unroll
        for (int i = 0; i < 8; ++i) s += red[i][t];
        g_Acoef[t * Kk + k] = s;
    }
}

// ------------------------------------------------------- K4: fused main
// grid 128 blocks x 512 threads (16 warps), 8 rows per block.
__global__ void __launch_bounds__(512) k_main(
    const float* __restrict__ tokens, const float* __restrict__ thr_p,
    const float* __restrict__ Gr, const float* __restrict__ Gi,
    const float* __restrict__ Lr, const float* __restrict__ Li,
    const float* __restrict__ E, const float* __restrict__ b2p,
    const float* __restrict__ gamma, const float* __restrict__ beta,
    float* __restrict__ out)
{
    __shared__ float xs[ROWS_PER_BLK * Dm];     // 32KB tokens (row-major)
    __shared__ float sp2[2][ROWS_PER_BLK * 128];// depth-half spectrum partials
    __shared__ float as2[Kk * ROWS_PER_BLK * 2];// weight*fr duplicated pairs [k][r][2]
    __shared__ float ac[NJ * Kk];
    __shared__ float red1[8][16], red2[8][16];
    __shared__ float rmean[8], rrstd[8];

    int t = threadIdx.x;
    int row0 = blockIdx.x * ROWS_PER_BLK;
    int w = t >> 5, lane = t & 31;

    // ---- stage tokens + coefficients
    {
        const float4* tok4 = (const float4*)(tokens + row0 * Dm);
        float4* xs4 = (float4*)xs;
        #pragma unroll
        for (int i = 0; i < 4; ++i) xs4[t + i * 512] = tok4[t + i * 512];
        for (int i = t; i < NJ * Kk; i += 512) ac[i] = g_Acoef[i];
    }
    __syncthreads();

    // ---- spectrum (tokens @ A): 16 warps; warp = (depth-half h, col-group cg).
    //      Each lane: 2 columns, depth stride 16 (4-lane split), all 8 rows.
    //      Each xs LDS.128 feeds 8 MACs (2 cols x 4 depths... per row pair of cols).
    {
        int h = w >> 3;                    // depth half 0/1
        int cg = w & 7;                    // col group: 16 cols
        int c0 = (cg << 4) + ((lane >> 2) << 1);
        int dbase = (h << 9) + ((lane & 3) << 2);
        float acc0[8], acc1[8];
        #pragma unroll
        for (int r = 0; r < 8; ++r) { acc0[r] = 0.f; acc1[r] = 0.f; }
        const float* A0 = g_AT + c0 * Dm;
        const float* A1 = A0 + Dm;
        #pragma unroll 2
        for (int it = 0; it < 32; ++it) {
            int d = dbase + (it << 4);
            float4 a0 = *(const float4*)&A0[d];
            float4 a1 = *(const float4*)&A1[d];
            #pragma unroll
            for (int r = 0; r < 8; ++r) {
                float4 xv = *(const float4*)&xs[r * Dm + d];
                acc0[r] = fmaf(xv.x, a0.x, acc0[r]);
                acc0[r] = fmaf(xv.y, a0.y, acc0[r]);
                acc0[r] = fmaf(xv.z, a0.z, acc0[r]);
                acc0[r] = fmaf(xv.w, a0.w, acc0[r]);
                acc1[r] = fmaf(xv.x, a1.x, acc1[r]);
                acc1[r] = fmaf(xv.y, a1.y, acc1[r]);
                acc1[r] = fmaf(xv.z, a1.z, acc1[r]);
                acc1[r] = fmaf(xv.w, a1.w, acc1[r]);
            }
        }
        #pragma unroll
        for (int r = 0; r < 8; ++r) {
            acc0[r] += __shfl_xor_sync(0xffffffffu, acc0[r], 1);
            acc0[r] += __shfl_xor_sync(0xffffffffu, acc0[r], 2);
            acc1[r] += __shfl_xor_sync(0xffffffffu, acc1[r], 1);
            acc1[r] += __shfl_xor_sync(0xffffffffu, acc1[r], 2);
        }
        if ((lane & 3) == 0) {
            #pragma unroll
            for (int r = 0; r < 8; ++r) {
                sp2[h][r * 128 + c0]     = acc0[r];
                sp2[h][r * 128 + c0 + 1] = acc1[r];
            }
        }
    }
    __syncthreads();

    float thr = thr_p[0];
    float b2v = b2p[0];

    // ---- filter + polynomial score: 512 threads = (r,k) pairs exactly.
    //      Each slot's reader == writer, so no extra sync needed before writes.
    {
        int r = t >> 6, k = t & 63;
        int c = (row0 + r) & 511;
        float re = sp2[0][r * 128 + k]      + sp2[1][r * 128 + k];
        float im = sp2[0][r * 128 + 64 + k] + sp2[1][r * 128 + 64 + k];
        float gr = Gr[c * Kk + k], gi = Gi[c * Kk + k];
        float lr = Lr[c * Kk + k], li = Li[c * Kk + k];
        float pw = fmaf(re, re, im * im);
        float fg = fmaf(re, gr, -im * gi);
        float fl = fmaf(re, lr, -im * li);
        float fr = (pw > thr) ? (fg + fl) : fg;
        float s = ac[10 * Kk + k];
        #pragma unroll
        for (int j = 9; j >= 0; --j) s = fmaf(s, fr, ac[j * Kk + k]);
        s += b2v;
        sp2[0][r * 128 + k]      = s;    // score
        sp2[0][r * 128 + 64 + k] = fr;   // fr
    }
    __syncthreads();

    // ---- softmax per row (warps 0..7), write duplicated (a,a) pairs
    if (w < 8) {
        float s0 = sp2[0][w * 128 + lane],      s1 = sp2[0][w * 128 + 32 + lane];
        float f0 = sp2[0][w * 128 + 64 + lane], f1 = sp2[0][w * 128 + 96 + lane];
        float mx = fmaxf(s0, s1);
        #pragma unroll
        for (int off = 16; off; off >>= 1)
            mx = fmaxf(mx, __shfl_xor_sync(0xffffffffu, mx, off));
        float e0 = __expf(s0 - mx), e1 = __expf(s1 - mx);
        float sm = e0 + e1;
        #pragma unroll
        for (int off = 16; off; off >>= 1)
            sm += __shfl_xor_sync(0xffffffffu, sm, off);
        float inv = 1.0f / sm;
        float a0 = e0 * inv * f0;
        float a1 = e1 * inv * f1;
        int i0 = (lane * 8 + w) * 2;
        int i1 = ((32 + lane) * 8 + w) * 2;
        as2[i0] = a0; as2[i0 + 1] = a0;
        as2[i1] = a1; as2[i1 + 1] = a1;
    }
    __syncthreads();

    // ---- pooled (f32x2 packed FMA) + LN, fully in registers
    {
        int d0 = t * 2;
        unsigned long long acc[8];
        #pragma unroll
        for (int r = 0; r < 8; ++r)
            acc[r] = *(const unsigned long long*)&xs[r * Dm + d0];
        #pragma unroll 4
        for (int k = 0; k < 64; ++k) {
            unsigned long long ev = *(const unsigned long long*)&E[k * Dm + d0];
            #pragma unroll
            for (int r = 0; r < 8; ++r) {
                unsigned long long aw = *(const unsigned long long*)&as2[(k * 8 + r) * 2];
                asm("fma.rn.f32x2 %0, %1, %2, %0;" : "+l"(acc[r]) : "l"(ev), "l"(aw));
            }
        }
        float2 v[8];
        #pragma unroll
        for (int r = 0; r < 8; ++r) {
            asm("mov.b64 {%0,%1}, %2;" : "=f"(v[r].x), "=f"(v[r].y) : "l"(acc[r]));
            float a = v[r].x + v[r].y;
            float b = fmaf(v[r].x, v[r].x, v[r].y * v[r].y);
            #pragma unroll
            for (int off = 16; off; off >>= 1) {
                a += __shfl_xor_sync(0xffffffffu, a, off);
                b += __shfl_xor_sync(0xffffffffu, b, off);
            }
            if (lane == 0) { red1[r][w] = a; red2[r][w] = b; }
        }
        __syncthreads();
        if (t < 8) {
            float s1 = 0.f, s2 = 0.f;
            #pragma unroll
            for (int i = 0; i < 16; ++i) { s1 += red1[t][i]; s2 += red2[t][i]; }
            float mean = s1 * (1.0f / 1024.0f);
            float var = fmaf(-mean, mean, s2 * (1.0f / 1024.0f));
            rmean[t] = mean;
            rrstd[t] = rsqrtf(var + 1e-5f);
        }
        __syncthreads();

        float2 g2 = *(const float2*)&gamma[d0];
        float2 b2g = *(const float2*)&beta[d0];
        #pragma unroll
        for (int r = 0; r < 8; ++r) {
            float mu = rmean[r], rs = rrstd[r];
            float2 o;
            o.x = fmaf((v[r].x - mu) * rs, g2.x, b2g.x);
            o.y = fmaf((v[r].y - mu) * rs, g2.y, b2g.y);
            *(float2*)&out[(row0 + r) * Dm + d0] = o;
        }
    }
}

// ---------------------------------------------------------------------------
extern "C" void kernel_launch(void* const* d_in, const int* in_sizes, int n_in,
                              void* d_out, int out_size) {
    const float* tokens = (const float*)d_in[0];
    const float* thresh = (const float*)d_in[1];
    const float* P      = (const float*)d_in[2];
    const float* Gr     = (const float*)d_in[3];
    const float* Gi     = (const float*)d_in[4];
    const float* Lr     = (const float*)d_in[5];
    const float* Li     = (const float*)d_in[6];
    const float* E      = (const float*)d_in[7];
    const float* W1     = (const float*)d_in[8];
    const float* b1     = (const float*)d_in[9];
    const float* w2     = (const float*)d_in[10];
    const float* b2     = (const float*)d_in[11];
    const float* gamma  = (const float*)d_in[12];
    const float* beta   = (const float*)d_in[13];
    float* out = (float*)d_out;

    k_buildA<<<128, 256>>>(P);
    k_gemm<<<128, 256>>>(E, W1);
    k_powred<<<64, 256>>>(b1, w2);
    k_main<<<NROWS / ROWS_PER_BLK, 512>>>(tokens, thresh, Gr, Gi, Lr, Li, E,
                                          b2, gamma, beta, out);
}

// round 8
// speedup vs baseline: 2.2554x; 1.0962x over previous
#include <cuda_runtime.h>
#include <cuda_bf16.h>

// ---------------------------------------------------------------------------
// AdaptiveSpectralBlock: B=2, C=512, D=1024, K=64, FB=513
//   spectrum = tokens @ A   (A precomputed from DFT x P, stored transposed)
//   fr = Re(spectrum*gw + spectrum*mask*lw)
//   score[k](t=fr) = b2 + sum_j t^j * Acoef[j][k]   (exact-GELU Taylor moments)
//   weights = softmax_k(score); pooled = (weights*fr) @ E; out = LN(tokens+pooled)
// ---------------------------------------------------------------------------

#define Dm 1024
#define Kk 64
#define FB 513
#define NROWS 1024            // B*C
#define ROWS_PER_BLK 8
#define NJ 11                 // poly degree 0..10
#define NSPLIT 8              // j-splits in E@W1 GEMM

typedef unsigned long long ull;

// scratch (allocation-free rule: __device__ globals)
__device__ float g_AT[128 * Dm];                // [col][d]; col 0..63 re, 64..127 im
__device__ float g_Mpart2[NSPLIT * Kk * Dm];    // partial m[k][d] per j-split
__device__ float g_Acoef[NJ * Kk];              // [j][k]

// gelu(y) = 0.5y + (1/sqrt(2pi)) (y^2 - y^4/6 + y^6/40 - y^8/336 + y^10/3456)
__constant__ float c_cp[NJ] = {
    0.0f, 0.5f,
    0.39894228040143270f, 0.0f,
   -0.06649038006690545f, 0.0f,
    0.00997355701003582f, 0.0f,
   -0.00118732821548045f, 0.0f,
    1.1543006956058354e-4f
};
__constant__ float c_binom[NJ][NJ] = {
    {1,0,0,0,0,0,0,0,0,0,0},
    {1,1,0,0,0,0,0,0,0,0,0},
    {1,2,1,0,0,0,0,0,0,0,0},
    {1,3,3,1,0,0,0,0,0,0,0},
    {1,4,6,4,1,0,0,0,0,0,0},
    {1,5,10,10,5,1,0,0,0,0,0},
    {1,6,15,20,15,6,1,0,0,0,0},
    {1,7,21,35,35,21,7,1,0,0,0},
    {1,8,28,56,70,56,28,8,1,0,0},
    {1,9,36,84,126,126,84,36,9,1,0},
    {1,10,45,120,210,252,210,120,45,10,1}
};

__device__ __forceinline__ void fma2(ull& acc, ull a, ull b) {
    asm("fma.rn.f32x2 %0, %1, %2, %0;" : "+l"(acc) : "l"(a), "l"(b));
}
__device__ __forceinline__ ull dup2(float v) {
    ull r;
    asm("mov.b64 %0, {%1, %1};" : "=l"(r) : "f"(v));
    return r;
}
__device__ __forceinline__ float2 unpack2(ull v) {
    float2 r;
    asm("mov.b64 {%0, %1}, %2;" : "=f"(r.x), "=f"(r.y) : "l"(v));
    return r;
}

// ------------------------------------------------- K1: A^T[col][d] = (trig @ P)^T
__global__ void __launch_bounds__(256) k_buildA(const float* __restrict__ P) {
    __shared__ float2 stw[Dm];            // (cos, -sin) twiddles
    __shared__ float sP[128 * 64];        // P f-tile
    int t = threadIdx.x;

    #pragma unroll
    for (int i = 0; i < 4; ++i) {
        int idx = t + i * 256;
        float s, c;
        sincospif((float)idx * (2.0f / (float)Dm), &s, &c);
        stw[idx] = make_float2(c, -s);
    }

    int k = t & 63, dq = t >> 6;
    int d0 = blockIdx.x * 8;
    int da = d0 + dq, db = da + 4;
    ull accA = 0ull, accB = 0ull;         // (re, im) f32x2 pairs
    int ia = 0, ib = 0;                   // (f*d) & 1023 recurrences

    const float4* P4 = (const float4*)P;
    for (int f0 = 0; f0 < 512; f0 += 128) {
        __syncthreads();
        #pragma unroll
        for (int i = 0; i < 8; ++i) {
            int lin4 = t + i * 256;
            ((float4*)sP)[lin4] = P4[f0 * 16 + lin4];
        }
        __syncthreads();
        #pragma unroll 4
        for (int ff = 0; ff < 128; ++ff) {
            ull wa = *(const ull*)&stw[ia];
            ull wb = *(const ull*)&stw[ib];
            ull pvd = dup2(sP[ff * 64 + k]);
            fma2(accA, wa, pvd);
            fma2(accB, wb, pvd);
            ia = (ia + da) & (Dm - 1);
            ib = (ib + db) & (Dm - 1);
        }
    }
    float2 ab = unpack2(accA);
    float2 bb = unpack2(accB);
    float ara = ab.x, aia = ab.y, arb = bb.x, aib = bb.y;

    float pn = P[512 * 64 + k];
    float sgn = (da & 1) ? -1.f : 1.f;
    ara = fmaf(sgn, pn, ara);
    arb = fmaf(sgn, pn, arb);

    g_AT[k * Dm + da]        = ara;
    g_AT[(64 + k) * Dm + da] = aia;
    g_AT[k * Dm + db]        = arb;
    g_AT[(64 + k) * Dm + db] = aib;
}

// --------------------- K2: m = E @ W1 split-K GEMM (partials per j-split)
__global__ void __launch_bounds__(256) k_gemm(const float* __restrict__ E,
                                              const float* __restrict__ W1) {
    __shared__ float sE[64 * 36];
    __shared__ float sW[32 * 64];
    int t = threadIdx.x;
    int bd = blockIdx.x & 15, bj = blockIdx.x >> 4;
    int d0 = bd * 64, j0 = bj * 128;
    int tk = (t >> 4) * 4;
    int tc = t & 15;
    int td = tc * 4;

    ull acc[4][2];                        // [row][d-pair]
    #pragma unroll
    for (int r = 0; r < 4; ++r) { acc[r][0] = 0ull; acc[r][1] = 0ull; }

    const float4* E4 = (const float4*)E;
    const float4* W14 = (const float4*)W1;

    for (int js = 0; js < 128; js += 32) {
        __syncthreads();
        #pragma unroll
        for (int i = 0; i < 2; ++i) {
            int lin4 = t + i * 256;
            int kr = lin4 >> 3, jc = lin4 & 7;
            float4 v = E4[kr * 256 + ((j0 + js) >> 2) + jc];
            *(float4*)&sE[kr * 36 + jc * 4] = v;
        }
        #pragma unroll
        for (int i = 0; i < 2; ++i) {
            int lin4 = t + i * 256;
            int jr = lin4 >> 4, dc = lin4 & 15;
            float4 v = W14[(j0 + js + jr) * 256 + (d0 >> 2) + dc];
            ((float4*)sW)[jr * 16 + dc] = v;
        }
        __syncthreads();
        #pragma unroll
        for (int jj = 0; jj < 32; ++jj) {
            ulonglong2 wp = ((const ulonglong2*)sW)[jj * 8 + tc];
            ull e0 = dup2(sE[(tk + 0) * 36 + jj]);
            ull e1 = dup2(sE[(tk + 1) * 36 + jj]);
            ull e2 = dup2(sE[(tk + 2) * 36 + jj]);
            ull e3 = dup2(sE[(tk + 3) * 36 + jj]);
            fma2(acc[0][0], e0, wp.x); fma2(acc[0][1], e0, wp.y);
            fma2(acc[1][0], e1, wp.x); fma2(acc[1][1], e1, wp.y);
            fma2(acc[2][0], e2, wp.x); fma2(acc[2][1], e2, wp.y);
            fma2(acc[3][0], e3, wp.x); fma2(acc[3][1], e3, wp.y);
        }
    }
    #pragma unroll
    for (int r = 0; r < 4; ++r) {
        ulonglong2 o; o.x = acc[r][0]; o.y = acc[r][1];
        *(ulonglong2*)&g_Mpart2[((bj << 6) + tk + r) * Dm + d0 + td] = o;
    }
}

// ----------- K3: reduce partials -> m; moments Acoef[j][k] (WG inline)
__global__ void __launch_bounds__(256) k_powred(const float* __restrict__ b1,
                                                const float* __restrict__ w2) {
    __shared__ float red[8][NJ];
    int k = blockIdx.x, t = threadIdx.x;
    int d = t * 4;
    int w = t >> 5, lane = t & 31;

    float4 m4 = make_float4(0.f, 0.f, 0.f, 0.f);
    #pragma unroll
    for (int p = 0; p < NSPLIT; ++p) {
        float4 v = *(const float4*)&g_Mpart2[((p << 6) + k) * Dm + d];
        m4.x += v.x; m4.y += v.y; m4.z += v.z; m4.w += v.w;
    }
    float4 b4 = *(const float4*)&b1[d];
    float4 w4 = *(const float4*)&w2[d];

    float accj[NJ];
    #pragma unroll
    for (int j = 0; j < NJ; ++j) accj[j] = 0.f;

    float mlane[4] = {m4.x, m4.y, m4.z, m4.w};
    float blane[4] = {b4.x, b4.y, b4.z, b4.w};
    float wlane[4] = {w4.x, w4.y, w4.z, w4.w};
    #pragma unroll
    for (int q = 0; q < 4; ++q) {
        float bb = blane[q], ww = wlane[q], mm = mlane[q];
        float bp[NJ];
        bp[0] = 1.f;
        #pragma unroll
        for (int i = 1; i < NJ; ++i) bp[i] = bp[i - 1] * bb;
        float mp = 1.f;
        #pragma unroll
        for (int j = 0; j < NJ; ++j) {
            float gj = 0.f;
            #pragma unroll
            for (int p = 0; p < NJ; ++p) {
                if (p >= j) gj = fmaf(c_cp[p] * c_binom[p][j], bp[p - j], gj);
            }
            accj[j] = fmaf(ww * gj, mp, accj[j]);
            mp *= mm;
        }
    }
    #pragma unroll
    for (int j = 0; j < NJ; ++j) {
        float a = accj[j];
        #pragma unroll
        for (int off = 16; off; off >>= 1)
            a += __shfl_xor_sync(0xffffffffu, a, off);
        if (lane == 0) red[w][j] = a;
    }
    __syncthreads();
    if (t < NJ) {
        float s = 0.f;
        #pragma unroll
        for (int i = 0; i < 8; ++i) s += red[i][t];
        g_Acoef[t * Kk + k] = s;
    }
}

// ------------------------------------------------------- K4: fused main
// grid 128 blocks x 512 threads (16 warps), 8 rows per block.
__global__ void __launch_bounds__(512) k_main(
    const float* __restrict__ tokens, const float* __restrict__ thr_p,
    const float* __restrict__ Gr, const float* __restrict__ Gi,
    const float* __restrict__ Lr, const float* __restrict__ Li,
    const float* __restrict__ E, const float* __restrict__ b2p,
    const float* __restrict__ gamma, const float* __restrict__ beta,
    float* __restrict__ out)
{
    __shared__ float xs[ROWS_PER_BLK * Dm];     // 32KB tokens (row-major)
    __shared__ float sp2[2][ROWS_PER_BLK * 128];// depth-half spectrum partials
    __shared__ float as2[Kk * ROWS_PER_BLK * 2];// weight*fr duplicated pairs [k][r][2]
    __shared__ float ac[NJ * Kk];
    __shared__ float red1[8][16], red2[8][16];
    __shared__ float rmean[8], rrstd[8];

    int t = threadIdx.x;
    int row0 = blockIdx.x * ROWS_PER_BLK;
    int w = t >> 5, lane = t & 31;

    // ---- stage tokens + coefficients
    {
        const float4* tok4 = (const float4*)(tokens + row0 * Dm);
        float4* xs4 = (float4*)xs;
        #pragma unroll
        for (int i = 0; i < 4; ++i) xs4[t + i * 512] = tok4[t + i * 512];
        for (int i = t; i < NJ * Kk; i += 512) ac[i] = g_Acoef[i];
    }
    __syncthreads();

    // ---- spectrum (tokens @ A): 16 warps = (depth-half h, col-group cg of 16).
    //      lane = (cg2 = lane>>3: 4-col quad, dpos = lane&7: 8-way depth split).
    //      4 cols/lane, f32x2 accumulation along depth pairs.
    {
        int h = w >> 3;                    // depth half 0/1
        int cg = w & 7;                    // 16-col group
        int cg2 = lane >> 3, dpos = lane & 7;
        int c0 = (cg << 4) + (cg2 << 2);   // first of 4 cols
        int dbase = (h << 9) + (dpos << 2);

        ull acc[8][4];
        #pragma unroll
        for (int r = 0; r < 8; ++r)
            #pragma unroll
            for (int q = 0; q < 4; ++q) acc[r][q] = 0ull;

        const float* A0 = g_AT + c0 * Dm + dbase;
        #pragma unroll 2
        for (int it = 0; it < 16; ++it) {
            int d = it << 5;               // +dbase implicit via pointers
            ulonglong2 a0 = *(const ulonglong2*)(A0 + d);
            ulonglong2 a1 = *(const ulonglong2*)(A0 + Dm + d);
            ulonglong2 a2 = *(const ulonglong2*)(A0 + 2 * Dm + d);
            ulonglong2 a3 = *(const ulonglong2*)(A0 + 3 * Dm + d);
            #pragma unroll
            for (int r = 0; r < 8; ++r) {
                ulonglong2 xp = *(const ulonglong2*)&xs[r * Dm + dbase + d];
                fma2(acc[r][0], xp.x, a0.x); fma2(acc[r][0], xp.y, a0.y);
                fma2(acc[r][1], xp.x, a1.x); fma2(acc[r][1], xp.y, a1.y);
                fma2(acc[r][2], xp.x, a2.x); fma2(acc[r][2], xp.y, a2.y);
                fma2(acc[r][3], xp.x, a3.x); fma2(acc[r][3], xp.y, a3.y);
            }
        }
        #pragma unroll
        for (int r = 0; r < 8; ++r) {
            #pragma unroll
            for (int q = 0; q < 4; ++q) {
                float2 p = unpack2(acc[r][q]);
                float s = p.x + p.y;
                s += __shfl_xor_sync(0xffffffffu, s, 1);
                s += __shfl_xor_sync(0xffffffffu, s, 2);
                s += __shfl_xor_sync(0xffffffffu, s, 4);
                if (dpos == 0) sp2[h][r * 128 + c0 + q] = s;
            }
        }
    }
    __syncthreads();

    float thr = thr_p[0];
    float b2v = b2p[0];

    // ---- filter + polynomial score: 512 threads = (r,k) pairs exactly.
    {
        int r = t >> 6, k = t & 63;
        int c = (row0 + r) & 511;
        float re = sp2[0][r * 128 + k]      + sp2[1][r * 128 + k];
        float im = sp2[0][r * 128 + 64 + k] + sp2[1][r * 128 + 64 + k];
        float gr = Gr[c * Kk + k], gi = Gi[c * Kk + k];
        float lr = Lr[c * Kk + k], li = Li[c * Kk + k];
        float pw = fmaf(re, re, im * im);
        float fg = fmaf(re, gr, -im * gi);
        float fl = fmaf(re, lr, -im * li);
        float fr = (pw > thr) ? (fg + fl) : fg;
        float s = ac[10 * Kk + k];
        #pragma unroll
        for (int j = 9; j >= 0; --j) s = fmaf(s, fr, ac[j * Kk + k]);
        s += b2v;
        sp2[0][r * 128 + k]      = s;    // score
        sp2[0][r * 128 + 64 + k] = fr;   // fr
    }
    __syncthreads();

    // ---- softmax per row (warps 0..7), write duplicated (a,a) pairs
    if (w < 8) {
        float s0 = sp2[0][w * 128 + lane],      s1 = sp2[0][w * 128 + 32 + lane];
        float f0 = sp2[0][w * 128 + 64 + lane], f1 = sp2[0][w * 128 + 96 + lane];
        float mx = fmaxf(s0, s1);
        #pragma unroll
        for (int off = 16; off; off >>= 1)
            mx = fmaxf(mx, __shfl_xor_sync(0xffffffffu, mx, off));
        float e0 = __expf(s0 - mx), e1 = __expf(s1 - mx);
        float sm = e0 + e1;
        #pragma unroll
        for (int off = 16; off; off >>= 1)
            sm += __shfl_xor_sync(0xffffffffu, sm, off);
        float inv = 1.0f / sm;
        float a0 = e0 * inv * f0;
        float a1 = e1 * inv * f1;
        int i0 = (lane * 8 + w) * 2;
        int i1 = ((32 + lane) * 8 + w) * 2;
        as2[i0] = a0; as2[i0 + 1] = a0;
        as2[i1] = a1; as2[i1 + 1] = a1;
    }
    __syncthreads();

    // ---- pooled (f32x2 packed FMA, LDS.128 weight pairs) + LN in registers
    {
        int d0 = t * 2;
        ull acc[8];
        #pragma unroll
        for (int r = 0; r < 8; ++r)
            acc[r] = *(const ull*)&xs[r * Dm + d0];
        #pragma unroll 4
        for (int k = 0; k < 64; ++k) {
            ull ev = *(const ull*)&E[k * Dm + d0];
            const ulonglong2* aw = (const ulonglong2*)&as2[k * 16];
            #pragma unroll
            for (int j = 0; j < 4; ++j) {
                ulonglong2 awp = aw[j];
                fma2(acc[2 * j],     ev, awp.x);
                fma2(acc[2 * j + 1], ev, awp.y);
            }
        }
        float2 v[8];
        #pragma unroll
        for (int r = 0; r < 8; ++r) {
            v[r] = unpack2(acc[r]);
            float a = v[r].x + v[r].y;
            float b = fmaf(v[r].x, v[r].x, v[r].y * v[r].y);
            #pragma unroll
            for (int off = 16; off; off >>= 1) {
                a += __shfl_xor_sync(0xffffffffu, a, off);
                b += __shfl_xor_sync(0xffffffffu, b, off);
            }
            if (lane == 0) { red1[r][w] = a; red2[r][w] = b; }
        }
        __syncthreads();
        if (t < 8) {
            float s1 = 0.f, s2 = 0.f;
            #pragma unroll
            for (int i = 0; i < 16; ++i) { s1 += red1[t][i]; s2 += red2[t][i]; }
            float mean = s1 * (1.0f / 1024.0f);
            float var = fmaf(-mean, mean, s2 * (1.0f / 1024.0f));
            rmean[t] = mean;
            rrstd[t] = rsqrtf(var + 1e-5f);
        }
        __syncthreads();

        float2 g2 = *(const float2*)&gamma[d0];
        float2 b2g = *(const float2*)&beta[d0];
        #pragma unroll
        for (int r = 0; r < 8; ++r) {
            float mu = rmean[r], rs = rrstd[r];
            float2 o;
            o.x = fmaf((v[r].x - mu) * rs, g2.x, b2g.x);
            o.y = fmaf((v[r].y - mu) * rs, g2.y, b2g.y);
            *(float2*)&out[(row0 + r) * Dm + d0] = o;
        }
    }
}

// ---------------------------------------------------------------------------
extern "C" void kernel_launch(void* const* d_in, const int* in_sizes, int n_in,
                              void* d_out, int out_size) {
    const float* tokens = (const float*)d_in[0];
    const float* thresh = (const float*)d_in[1];
    const float* P      = (const float*)d_in[2];
    const float* Gr     = (const float*)d_in[3];
    const float* Gi     = (const float*)d_in[4];
    const float* Lr     = (const float*)d_in[5];
    const float* Li     = (const float*)d_in[6];
    const float* E      = (const float*)d_in[7];
    const float* W1     = (const float*)d_in[8];
    const float* b1     = (const float*)d_in[9];
    const float* w2     = (const float*)d_in[10];
    const float* b2     = (const float*)d_in[11];
    const float* gamma  = (const float*)d_in[12];
    const float* beta   = (const float*)d_in[13];
    float* out = (float*)d_out;

    k_buildA<<<128, 256>>>(P);
    k_gemm<<<128, 256>>>(E, W1);
    k_powred<<<64, 256>>>(b1, w2);
    k_main<<<NROWS / ROWS_PER_BLK, 512>>>(tokens, thresh, Gr, Gi, Lr, Li, E,
                                          b2, gamma, beta, out);
}

// round 9
// speedup vs baseline: 2.2631x; 1.0034x over previous
#include <cuda_runtime.h>
#include <cuda_bf16.h>

// ---------------------------------------------------------------------------
// AdaptiveSpectralBlock: B=2, C=512, D=1024, K=64, FB=513
//   spectrum = tokens @ A   (A precomputed from DFT x P, stored transposed)
//   fr = Re(spectrum*gw + spectrum*mask*lw)
//   score[k](t=fr) = b2 + sum_j t^j * Acoef[j][k]   (exact-GELU Taylor moments)
//   weights = softmax_k(score); pooled = (weights*fr) @ E; out = LN(tokens+pooled)
// ---------------------------------------------------------------------------

#define Dm 1024
#define Kk 64
#define FB 513
#define NROWS 1024            // B*C
#define RPB 4                 // rows per k_main block
#define NJ 11                 // poly degree 0..10
#define NSPLIT 8              // j-splits in E@W1 GEMM

typedef unsigned long long ull;

// scratch (allocation-free rule: __device__ globals)
__device__ float g_AT[128 * Dm];                // [col][d]; col 0..63 re, 64..127 im
__device__ float g_Mpart2[NSPLIT * Kk * Dm];    // partial m[k][d] per j-split
__device__ float g_Acoef[NJ * Kk];              // [j][k]

// gelu(y) = 0.5y + (1/sqrt(2pi)) (y^2 - y^4/6 + y^6/40 - y^8/336 + y^10/3456)
__constant__ float c_cp[NJ] = {
    0.0f, 0.5f,
    0.39894228040143270f, 0.0f,
   -0.06649038006690545f, 0.0f,
    0.00997355701003582f, 0.0f,
   -0.00118732821548045f, 0.0f,
    1.1543006956058354e-4f
};
__constant__ float c_binom[NJ][NJ] = {
    {1,0,0,0,0,0,0,0,0,0,0},
    {1,1,0,0,0,0,0,0,0,0,0},
    {1,2,1,0,0,0,0,0,0,0,0},
    {1,3,3,1,0,0,0,0,0,0,0},
    {1,4,6,4,1,0,0,0,0,0,0},
    {1,5,10,10,5,1,0,0,0,0,0},
    {1,6,15,20,15,6,1,0,0,0,0},
    {1,7,21,35,35,21,7,1,0,0,0},
    {1,8,28,56,70,56,28,8,1,0,0},
    {1,9,36,84,126,126,84,36,9,1,0},
    {1,10,45,120,210,252,210,120,45,10,1}
};

__device__ __forceinline__ void fma2(ull& acc, ull a, ull b) {
    asm("fma.rn.f32x2 %0, %1, %2, %0;" : "+l"(acc) : "l"(a), "l"(b));
}
__device__ __forceinline__ ull dup2(float v) {
    ull r;
    asm("mov.b64 %0, {%1, %1};" : "=l"(r) : "f"(v));
    return r;
}
__device__ __forceinline__ float2 unpack2(ull v) {
    float2 r;
    asm("mov.b64 {%0, %1}, %2;" : "=f"(r.x), "=f"(r.y) : "l"(v));
    return r;
}

// ---------------------------------------------------------------------------
// K_pre: fused precompute.
//   blocks [0,128):   A^T[col][d] = (trig @ P)^T     (buildA role)
//   blocks [128,256): m = E @ W1 split-K GEMM partials (gemm role)
// Both roles use 256 threads; smem is a union (40KB).
// ---------------------------------------------------------------------------
__global__ void __launch_bounds__(256) k_pre(const float* __restrict__ P,
                                             const float* __restrict__ E,
                                             const float* __restrict__ W1) {
    __shared__ __align__(16) char sm[40960];
    int t = threadIdx.x;

    if (blockIdx.x < 128) {
        // ---------------- buildA role ----------------
        float2* stw = (float2*)sm;                 // 8KB twiddles (cos, -sin)
        float*  sP  = (float*)(sm + 8192);         // 32KB P f-tile

        #pragma unroll
        for (int i = 0; i < 4; ++i) {
            int idx = t + i * 256;
            float s, c;
            sincospif((float)idx * (2.0f / (float)Dm), &s, &c);
            stw[idx] = make_float2(c, -s);
        }

        int k = t & 63, dq = t >> 6;
        int d0 = blockIdx.x * 8;
        int da = d0 + dq, db = da + 4;
        ull accA = 0ull, accB = 0ull;              // (re, im) pairs
        int ia = 0, ib = 0;                        // (f*d) & 1023 recurrences

        const float4* P4 = (const float4*)P;
        for (int f0 = 0; f0 < 512; f0 += 128) {
            __syncthreads();
            #pragma unroll
            for (int i = 0; i < 8; ++i) {
                int lin4 = t + i * 256;
                ((float4*)sP)[lin4] = P4[f0 * 16 + lin4];
            }
            __syncthreads();
            #pragma unroll 4
            for (int ff = 0; ff < 128; ++ff) {
                ull wa = *(const ull*)&stw[ia];
                ull wb = *(const ull*)&stw[ib];
                ull pvd = dup2(sP[ff * 64 + k]);
                fma2(accA, wa, pvd);
                fma2(accB, wb, pvd);
                ia = (ia + da) & (Dm - 1);
                ib = (ib + db) & (Dm - 1);
            }
        }
        float2 ab = unpack2(accA);
        float2 bb = unpack2(accB);
        float ara = ab.x, aia = ab.y, arb = bb.x, aib = bb.y;

        float pn = P[512 * 64 + k];                // Nyquist: cos=(-1)^d, sin=0
        float sgn = (da & 1) ? -1.f : 1.f;
        ara = fmaf(sgn, pn, ara);
        arb = fmaf(sgn, pn, arb);

        g_AT[k * Dm + da]        = ara;
        g_AT[(64 + k) * Dm + da] = aia;
        g_AT[k * Dm + db]        = arb;
        g_AT[(64 + k) * Dm + db] = aib;
    } else {
        // ---------------- gemm role ----------------
        float* sE = (float*)sm;                    // 64x36 (9216B)
        float* sW = (float*)(sm + 9216);           // 32x64 (8192B)
        int bid = blockIdx.x - 128;
        int bd = bid & 15, bj = bid >> 4;
        int d0 = bd * 64, j0 = bj * 128;
        int tk = (t >> 4) * 4;
        int tc = t & 15;
        int td = tc * 4;

        ull acc[4][2];
        #pragma unroll
        for (int r = 0; r < 4; ++r) { acc[r][0] = 0ull; acc[r][1] = 0ull; }

        const float4* E4 = (const float4*)E;
        const float4* W14 = (const float4*)W1;

        for (int js = 0; js < 128; js += 32) {
            __syncthreads();
            #pragma unroll
            for (int i = 0; i < 2; ++i) {
                int lin4 = t + i * 256;
                int kr = lin4 >> 3, jc = lin4 & 7;
                float4 v = E4[kr * 256 + ((j0 + js) >> 2) + jc];
                *(float4*)&sE[kr * 36 + jc * 4] = v;
            }
            #pragma unroll
            for (int i = 0; i < 2; ++i) {
                int lin4 = t + i * 256;
                int jr = lin4 >> 4, dc = lin4 & 15;
                float4 v = W14[(j0 + js + jr) * 256 + (d0 >> 2) + dc];
                ((float4*)sW)[jr * 16 + dc] = v;
            }
            __syncthreads();
            #pragma unroll
            for (int jj = 0; jj < 32; ++jj) {
                ulonglong2 wp = ((const ulonglong2*)sW)[jj * 8 + tc];
                ull e0 = dup2(sE[(tk + 0) * 36 + jj]);
                ull e1 = dup2(sE[(tk + 1) * 36 + jj]);
                ull e2 = dup2(sE[(tk + 2) * 36 + jj]);
                ull e3 = dup2(sE[(tk + 3) * 36 + jj]);
                fma2(acc[0][0], e0, wp.x); fma2(acc[0][1], e0, wp.y);
                fma2(acc[1][0], e1, wp.x); fma2(acc[1][1], e1, wp.y);
                fma2(acc[2][0], e2, wp.x); fma2(acc[2][1], e2, wp.y);
                fma2(acc[3][0], e3, wp.x); fma2(acc[3][1], e3, wp.y);
            }
        }
        #pragma unroll
        for (int r = 0; r < 4; ++r) {
            ulonglong2 o; o.x = acc[r][0]; o.y = acc[r][1];
            *(ulonglong2*)&g_Mpart2[((bj << 6) + tk + r) * Dm + d0 + td] = o;
        }
    }
}

// ----------- K2: reduce partials -> m; moments Acoef[j][k] (WG inline)
__global__ void __launch_bounds__(256) k_powred(const float* __restrict__ b1,
                                                const float* __restrict__ w2) {
    __shared__ float red[8][NJ];
    int k = blockIdx.x, t = threadIdx.x;
    int d = t * 4;
    int w = t >> 5, lane = t & 31;

    float4 m4 = make_float4(0.f, 0.f, 0.f, 0.f);
    #pragma unroll
    for (int p = 0; p < NSPLIT; ++p) {
        float4 v = *(const float4*)&g_Mpart2[((p << 6) + k) * Dm + d];
        m4.x += v.x; m4.y += v.y; m4.z += v.z; m4.w += v.w;
    }
    float4 b4 = *(const float4*)&b1[d];
    float4 w4 = *(const float4*)&w2[d];

    float accj[NJ];
    #pragma unroll
    for (int j = 0; j < NJ; ++j) accj[j] = 0.f;

    float mlane[4] = {m4.x, m4.y, m4.z, m4.w};
    float blane[4] = {b4.x, b4.y, b4.z, b4.w};
    float wlane[4] = {w4.x, w4.y, w4.z, w4.w};
    #pragma unroll
    for (int q = 0; q < 4; ++q) {
        float bb = blane[q], ww = wlane[q], mm = mlane[q];
        float bp[NJ];
        bp[0] = 1.f;
        #pragma unroll
        for (int i = 1; i < NJ; ++i) bp[i] = bp[i - 1] * bb;
        float mp = 1.f;
        #pragma unroll
        for (int j = 0; j < NJ; ++j) {
            float gj = 0.f;
            #pragma unroll
            for (int p = 0; p < NJ; ++p) {
                if (p >= j) gj = fmaf(c_cp[p] * c_binom[p][j], bp[p - j], gj);
            }
            accj[j] = fmaf(ww * gj, mp, accj[j]);
            mp *= mm;
        }
    }
    #pragma unroll
    for (int j = 0; j < NJ; ++j) {
        float a = accj[j];
        #pragma unroll
        for (int off = 16; off; off >>= 1)
            a += __shfl_xor_sync(0xffffffffu, a, off);
        if (lane == 0) red[w][j] = a;
    }
    __syncthreads();
    if (t < NJ) {
        float s = 0.f;
        #pragma unroll
        for (int i = 0; i < 8; ++i) s += red[i][t];
        g_Acoef[t * Kk + k] = s;
    }
}

// ------------------------------------------------------- K3: fused main
// grid 256 blocks x 512 threads, 4 rows per block, 2 CTAs/SM.
__global__ void __launch_bounds__(512, 2) k_main(
    const float* __restrict__ tokens, const float* __restrict__ thr_p,
    const float* __restrict__ Gr, const float* __restrict__ Gi,
    const float* __restrict__ Lr, const float* __restrict__ Li,
    const float* __restrict__ E, const float* __restrict__ b2p,
    const float* __restrict__ gamma, const float* __restrict__ beta,
    float* __restrict__ out)
{
    __shared__ float xs[RPB * Dm];              // 16KB tokens
    __shared__ float sp2[2][RPB * 128];         // depth-half spectrum partials
    __shared__ float as2[Kk * RPB * 2];         // weight*fr dup pairs [k][r][2]
    __shared__ float ac[NJ * Kk];
    __shared__ float red1[RPB][16], red2[RPB][16];
    __shared__ float rmean[RPB], rrstd[RPB];

    int t = threadIdx.x;
    int row0 = blockIdx.x * RPB;
    int w = t >> 5, lane = t & 31;

    // ---- stage tokens + coefficients
    {
        const float4* tok4 = (const float4*)(tokens + row0 * Dm);
        float4* xs4 = (float4*)xs;
        #pragma unroll
        for (int i = 0; i < 2; ++i) xs4[t + i * 512] = tok4[t + i * 512];
        for (int i = t; i < NJ * Kk; i += 512) ac[i] = g_Acoef[i];
    }
    __syncthreads();

    // ---- spectrum (tokens @ A): 16 warps = (half h, col-group cg of 16).
    //      lane: cg2 = lane>>3 (4-col quad), dpos = lane&7 (8-way depth).
    //      4 rows x 4 cols per lane, f32x2 along depth pairs.
    {
        int h = w >> 3;
        int cg = w & 7;
        int cg2 = lane >> 3, dpos = lane & 7;
        int c0 = (cg << 4) + (cg2 << 2);
        int dbase = (h << 9) + (dpos << 2);

        ull acc[RPB][4];
        #pragma unroll
        for (int r = 0; r < RPB; ++r)
            #pragma unroll
            for (int q = 0; q < 4; ++q) acc[r][q] = 0ull;

        const float* A0 = g_AT + c0 * Dm + dbase;
        #pragma unroll 2
        for (int it = 0; it < 16; ++it) {
            int d = it << 5;
            ulonglong2 a0 = *(const ulonglong2*)(A0 + d);
            ulonglong2 a1 = *(const ulonglong2*)(A0 + Dm + d);
            ulonglong2 a2 = *(const ulonglong2*)(A0 + 2 * Dm + d);
            ulonglong2 a3 = *(const ulonglong2*)(A0 + 3 * Dm + d);
            #pragma unroll
            for (int r = 0; r < RPB; ++r) {
                ulonglong2 xp = *(const ulonglong2*)&xs[r * Dm + dbase + d];
                fma2(acc[r][0], xp.x, a0.x); fma2(acc[r][0], xp.y, a0.y);
                fma2(acc[r][1], xp.x, a1.x); fma2(acc[r][1], xp.y, a1.y);
                fma2(acc[r][2], xp.x, a2.x); fma2(acc[r][2], xp.y, a2.y);
                fma2(acc[r][3], xp.x, a3.x); fma2(acc[r][3], xp.y, a3.y);
            }
        }
        #pragma unroll
        for (int r = 0; r < RPB; ++r) {
            #pragma unroll
            for (int q = 0; q < 4; ++q) {
                float2 p = unpack2(acc[r][q]);
                float s = p.x + p.y;
                s += __shfl_xor_sync(0xffffffffu, s, 1);
                s += __shfl_xor_sync(0xffffffffu, s, 2);
                s += __shfl_xor_sync(0xffffffffu, s, 4);
                if (dpos == 0) sp2[h][r * 128 + c0 + q] = s;
            }
        }
    }
    __syncthreads();

    float thr = thr_p[0];
    float b2v = b2p[0];

    // ---- filter + polynomial score: threads 0..255 own (r,k) pairs
    if (t < RPB * 64) {
        int r = t >> 6, k = t & 63;
        int c = (row0 + r) & 511;
        float re = sp2[0][r * 128 + k]      + sp2[1][r * 128 + k];
        float im = sp2[0][r * 128 + 64 + k] + sp2[1][r * 128 + 64 + k];
        float gr = Gr[c * Kk + k], gi = Gi[c * Kk + k];
        float lr = Lr[c * Kk + k], li = Li[c * Kk + k];
        float pw = fmaf(re, re, im * im);
        float fg = fmaf(re, gr, -im * gi);
        float fl = fmaf(re, lr, -im * li);
        float fr = (pw > thr) ? (fg + fl) : fg;
        float s = ac[10 * Kk + k];
        #pragma unroll
        for (int j = 9; j >= 0; --j) s = fmaf(s, fr, ac[j * Kk + k]);
        s += b2v;
        sp2[0][r * 128 + k]      = s;    // score
        sp2[0][r * 128 + 64 + k] = fr;   // fr
    }
    __syncthreads();

    // ---- softmax per row (warps 0..3), write duplicated (a,a) pairs
    if (w < RPB) {
        float s0 = sp2[0][w * 128 + lane],      s1 = sp2[0][w * 128 + 32 + lane];
        float f0 = sp2[0][w * 128 + 64 + lane], f1 = sp2[0][w * 128 + 96 + lane];
        float mx = fmaxf(s0, s1);
        #pragma unroll
        for (int off = 16; off; off >>= 1)
            mx = fmaxf(mx, __shfl_xor_sync(0xffffffffu, mx, off));
        float e0 = __expf(s0 - mx), e1 = __expf(s1 - mx);
        float sm = e0 + e1;
        #pragma unroll
        for (int off = 16; off; off >>= 1)
            sm += __shfl_xor_sync(0xffffffffu, sm, off);
        float inv = 1.0f / sm;
        float a0 = e0 * inv * f0;
        float a1 = e1 * inv * f1;
        int i0 = lane * (RPB * 2) + w * 2;
        int i1 = (32 + lane) * (RPB * 2) + w * 2;
        as2[i0] = a0; as2[i0 + 1] = a0;
        as2[i1] = a1; as2[i1 + 1] = a1;
    }
    __syncthreads();

    // ---- pooled (f32x2 packed FMA) + LN in registers
    {
        int d0 = t * 2;
        ull acc[RPB];
        #pragma unroll
        for (int r = 0; r < RPB; ++r)
            acc[r] = *(const ull*)&xs[r * Dm + d0];
        #pragma unroll 4
        for (int k = 0; k < 64; ++k) {
            ull ev = *(const ull*)&E[k * Dm + d0];
            const ulonglong2* aw = (const ulonglong2*)&as2[k * (RPB * 2)];
            ulonglong2 aw01 = aw[0];
            ulonglong2 aw23 = aw[1];
            fma2(acc[0], ev, aw01.x);
            fma2(acc[1], ev, aw01.y);
            fma2(acc[2], ev, aw23.x);
            fma2(acc[3], ev, aw23.y);
        }
        float2 v[RPB];
        #pragma unroll
        for (int r = 0; r < RPB; ++r) {
            v[r] = unpack2(acc[r]);
            float a = v[r].x + v[r].y;
            float b = fmaf(v[r].x, v[r].x, v[r].y * v[r].y);
            #pragma unroll
            for (int off = 16; off; off >>= 1) {
                a += __shfl_xor_sync(0xffffffffu, a, off);
                b += __shfl_xor_sync(0xffffffffu, b, off);
            }
            if (lane == 0) { red1[r][w] = a; red2[r][w] = b; }
        }
        __syncthreads();
        if (t < RPB) {
            float s1 = 0.f, s2 = 0.f;
            #pragma unroll
            for (int i = 0; i < 16; ++i) { s1 += red1[t][i]; s2 += red2[t][i]; }
            float mean = s1 * (1.0f / 1024.0f);
            float var = fmaf(-mean, mean, s2 * (1.0f / 1024.0f));
            rmean[t] = mean;
            rrstd[t] = rsqrtf(var + 1e-5f);
        }
        __syncthreads();

        float2 g2 = *(const float2*)&gamma[d0];
        float2 b2g = *(const float2*)&beta[d0];
        #pragma unroll
        for (int r = 0; r < RPB; ++r) {
            float mu = rmean[r], rs = rrstd[r];
            float2 o;
            o.x = fmaf((v[r].x - mu) * rs, g2.x, b2g.x);
            o.y = fmaf((v[r].y - mu) * rs, g2.y, b2g.y);
            *(float2*)&out[(row0 + r) * Dm + d0] = o;
        }
    }
}

// ---------------------------------------------------------------------------
extern "C" void kernel_launch(void* const* d_in, const int* in_sizes, int n_in,
                              void* d_out, int out_size) {
    const float* tokens = (const float*)d_in[0];
    const float* thresh = (const float*)d_in[1];
    const float* P      = (const float*)d_in[2];
    const float* Gr     = (const float*)d_in[3];
    const float* Gi     = (const float*)d_in[4];
    const float* Lr     = (const float*)d_in[5];
    const float* Li     = (const float*)d_in[6];
    const float* E      = (const float*)d_in[7];
    const float* W1     = (const float*)d_in[8];
    const float* b1     = (const float*)d_in[9];
    const float* w2     = (const float*)d_in[10];
    const float* b2     = (const float*)d_in[11];
    const float* gamma  = (const float*)d_in[12];
    const float* beta   = (const float*)d_in[13];
    float* out = (float*)d_out;

    k_pre<<<256, 256>>>(P, E, W1);
    k_powred<<<64, 256>>>(b1, w2);
    k_main<<<NROWS / RPB, 512>>>(tokens, thresh, Gr, Gi, Lr, Li, E,
                                 b2, gamma, beta, out);
}